// round 14
// baseline (speedup 1.0000x reference)
#include <cuda_runtime.h>
#include <cuda_fp16.h>
#include <cstdint>
#include <math.h>

// ---------------- problem constants ----------------
#define BB     4
#define LL     4096
#define DD     1024
#define AD     64
#define WW     64
#define FFD    2048
#define MROWS  (BB*LL)
#define CHUNK  64
#define NCHUNK (LL/CHUNK)
#define EPSR   1e-6f
#define QKVN   256         // q|k|v|gate padded width

// ---------------- scratch ----------------
__device__ float  g_xssm[(size_t)MROWS*DD];
__device__ float  g_rinv[MROWS];
__device__ __half g_xh[(size_t)MROWS*DD];
__device__ __half g_n2h[(size_t)MROWS*DD];
__device__ __half g_tmp[(size_t)MROWS*FFD];
__device__ __half g_ga[(size_t)MROWS*AD];
__device__ float  g_agg[(size_t)BB*NCHUNK*DD];
__device__ float  g_incl[(size_t)BB*NCHUNK*DD];
__device__ int    g_flags[BB*NCHUNK*2];
__device__ __half g_qkvh[(size_t)MROWS*QKVN];
__device__ __half g_wqkvT[(size_t)QKVN*DD];
__device__ __half g_woT[(size_t)DD*AD];
__device__ __half g_f1T[(size_t)FFD*DD];
__device__ __half g_f2T[(size_t)DD*FFD];

__device__ __forceinline__ float sigmoidf_(float x) { return 1.0f / (1.0f + expf(-x)); }

__device__ __forceinline__ uint32_t smem_u32(const void* p) {
    uint32_t a;
    asm("{ .reg .u64 t; cvta.to.shared.u64 t, %1; cvt.u32.u64 %0, t; }" : "=r"(a) : "l"(p));
    return a;
}
__device__ __forceinline__ void cp16(uint32_t dst, const void* src) {
    asm volatile("cp.async.cg.shared.global [%0], [%1], 16;" :: "r"(dst), "l"(src));
}
__device__ __forceinline__ void cp_commit() { asm volatile("cp.async.commit_group;"); }
template <int N> __device__ __forceinline__ void cp_wait() {
    asm volatile("cp.async.wait_group %0;" :: "n"(N) : "memory");
}
__device__ __forceinline__ void ldsm4(uint32_t addr, uint32_t& r0, uint32_t& r1,
                                      uint32_t& r2, uint32_t& r3) {
    asm volatile("ldmatrix.sync.aligned.m8n8.x4.shared.b16 {%0,%1,%2,%3}, [%4];"
                 : "=r"(r0), "=r"(r1), "=r"(r2), "=r"(r3) : "r"(addr));
}
__device__ __forceinline__ void mma_f16(float* c, const uint32_t* a, const uint32_t* b) {
    asm volatile("mma.sync.aligned.m16n8k16.row.col.f32.f16.f16.f32 "
                 "{%0,%1,%2,%3}, {%4,%5,%6,%7}, {%8,%9}, {%0,%1,%2,%3};"
                 : "+f"(c[0]), "+f"(c[1]), "+f"(c[2]), "+f"(c[3])
                 : "r"(a[0]), "r"(a[1]), "r"(a[2]), "r"(a[3]), "r"(b[0]), "r"(b[1]));
}

// ====== GEMM-A: 8 warps (4x2), BM=128, BN=128, BK=64. For Wo (memory-bound, K=64). ======
// EPI 2 = +resid fp32 C
__global__ __launch_bounds__(256, 2) void mma_gemm8(
    int N, int K,
    const __half* __restrict__ A, const __half* __restrict__ B,
    float* __restrict__ Cf, const float* __restrict__ resid)
{
    constexpr int BN = 128;
    constexpr int NT = BN / 16;
    constexpr int A_BYTES = 128 * 128;
    constexpr int B_BYTES = BN * 128;
    constexpr int STAGE = A_BYTES + B_BYTES;

    extern __shared__ __align__(128) char smem[];
    uint32_t sb = smem_u32(smem);

    const int tid  = threadIdx.x;
    const int lane = tid & 31;
    const int wid  = tid >> 5;
    const int wr   = wid & 3;
    const int wc   = wid >> 2;

    const __half* Ab = A + (size_t)blockIdx.y * 128 * K;
    const __half* Bb = B + (size_t)blockIdx.x * BN * K;

    const int NIT = K >> 6;

    auto load_stage = [&](int s, int kb) {
        uint32_t base = sb + s * STAGE;
        const __half* g = Ab + kb;
        #pragma unroll
        for (int i = tid; i < 1024; i += 256) {
            int r = i >> 3, kc = i & 7;
            cp16(base + r * 128 + ((kc ^ (r & 7)) << 4), g + (size_t)r * K + kc * 8);
        }
        g = Bb + kb;
        uint32_t bdst = base + A_BYTES;
        #pragma unroll
        for (int i = tid; i < BN * 8; i += 256) {
            int r = i >> 3, kc = i & 7;
            cp16(bdst + r * 128 + ((kc ^ (r & 7)) << 4), g + (size_t)r * K + kc * 8);
        }
    };

    auto ld_afrag = [&](uint32_t abase, int ks, uint32_t af[2][4]) {
        #pragma unroll
        for (int mt = 0; mt < 2; mt++) {
            int row = wr * 32 + mt * 16 + (lane & 15);
            int kc  = ks * 2 + (lane >> 4);
            uint32_t off = row * 128 + ((kc ^ (row & 7)) << 4);
            ldsm4(abase + off, af[mt][0], af[mt][1], af[mt][2], af[mt][3]);
        }
    };
    auto ld_bfrag = [&](uint32_t bbase, int ks, uint32_t bf[NT][2]) {
        #pragma unroll
        for (int np = 0; np < NT / 2; np++) {
            int n  = wc * (BN / 2) + np * 16 + ((lane >> 4) << 3) + (lane & 7);
            int kc = ks * 2 + ((lane >> 3) & 1);
            uint32_t off = n * 128 + ((kc ^ (n & 7)) << 4);
            ldsm4(bbase + off, bf[2*np][0], bf[2*np][1], bf[2*np+1][0], bf[2*np+1][1]);
        }
    };

    float acc[2][NT][4];
    #pragma unroll
    for (int mt = 0; mt < 2; mt++)
        #pragma unroll
        for (int nt = 0; nt < NT; nt++)
            #pragma unroll
            for (int j = 0; j < 4; j++) acc[mt][nt][j] = 0.f;

    load_stage(0, 0);
    cp_commit();
    if (NIT > 1) { load_stage(1, 64); cp_commit(); }

    for (int it = 0; it < NIT; it++) {
        if (it + 1 < NIT) cp_wait<1>(); else cp_wait<0>();
        __syncthreads();
        if (it + 2 < NIT) {
            load_stage((it + 2) % 3, (it + 2) << 6);
            cp_commit();
        }

        uint32_t abase = sb + (it % 3) * STAGE;
        uint32_t bbase = abase + A_BYTES;

        uint32_t ah[2][2][4], bbf[NT][2];
        ld_afrag(abase, 0, ah[0]);
        #pragma unroll
        for (int ks = 0; ks < 4; ks++) {
            int cur = ks & 1, nxt = cur ^ 1;
            ld_bfrag(bbase, ks, bbf);
            if (ks < 3) ld_afrag(abase, ks + 1, ah[nxt]);
            #pragma unroll
            for (int mt = 0; mt < 2; mt++)
                #pragma unroll
                for (int nt = 0; nt < NT; nt++) mma_f16(acc[mt][nt], ah[cur][mt], bbf[nt]);
        }
    }

    int rowbase = blockIdx.y * 128 + wr * 32;
    int colbase = blockIdx.x * BN + wc * (BN / 2);
    #pragma unroll
    for (int mt = 0; mt < 2; mt++) {
        #pragma unroll
        for (int nt = 0; nt < NT; nt++) {
            int m = rowbase + mt * 16 + (lane >> 2);
            int n = colbase + nt * 8 + ((lane & 3) << 1);
            float* cc = acc[mt][nt];
            #pragma unroll
            for (int half = 0; half < 2; half++) {
                size_t idx = (size_t)(m + half * 8) * N + n;
                float2 r2 = *(const float2*)(resid + idx);
                float2 o = { cc[half * 2] + r2.x, cc[half * 2 + 1] + r2.y };
                *(float2*)(Cf + idx) = o;
            }
        }
    }
}

// ====== GEMM-B: 4 warps (2x2), BM=BN=128, warp 64x64 (crossbar-optimal, 306 TF/s). ======
// EPI: 0 = fp16 C plain; 1 = silu + fp16 C; 2 = +resid fp32 C
template <int EPI>
__global__ __launch_bounds__(128, 2) void mma_gemm4(
    int N, int K,
    const __half* __restrict__ A, const __half* __restrict__ B,
    float* __restrict__ Cf, __half* __restrict__ Ch,
    const float* __restrict__ resid)
{
    constexpr int A_BYTES = 128 * 128;
    constexpr int STAGE = 2 * A_BYTES;   // 32 KB

    extern __shared__ __align__(128) char smem[];
    uint32_t sb = smem_u32(smem);

    const int tid  = threadIdx.x;
    const int lane = tid & 31;
    const int wid  = tid >> 5;
    const int wr   = wid & 1;
    const int wc   = wid >> 1;

    const __half* Ab = A + (size_t)blockIdx.y * 128 * K;
    const __half* Bb = B + (size_t)blockIdx.x * 128 * K;

    const int NIT = K >> 6;

    auto load_stage = [&](int s, int kb) {
        uint32_t base = sb + s * STAGE;
        const __half* g = Ab + kb;
        #pragma unroll
        for (int i = tid; i < 1024; i += 128) {
            int r = i >> 3, kc = i & 7;
            cp16(base + r * 128 + ((kc ^ (r & 7)) << 4), g + (size_t)r * K + kc * 8);
        }
        g = Bb + kb;
        uint32_t bdst = base + A_BYTES;
        #pragma unroll
        for (int i = tid; i < 1024; i += 128) {
            int r = i >> 3, kc = i & 7;
            cp16(bdst + r * 128 + ((kc ^ (r & 7)) << 4), g + (size_t)r * K + kc * 8);
        }
    };

    float acc[4][8][4];
    #pragma unroll
    for (int mt = 0; mt < 4; mt++)
        #pragma unroll
        for (int nt = 0; nt < 8; nt++)
            #pragma unroll
            for (int j = 0; j < 4; j++) acc[mt][nt][j] = 0.f;

    load_stage(0, 0);
    cp_commit();
    if (NIT > 1) { load_stage(1, 64); cp_commit(); }

    for (int it = 0; it < NIT; it++) {
        if (it + 1 < NIT) cp_wait<1>(); else cp_wait<0>();
        __syncthreads();
        if (it + 2 < NIT) {
            load_stage((it + 2) % 3, (it + 2) << 6);
            cp_commit();
        }

        uint32_t abase = sb + (it % 3) * STAGE;
        uint32_t bbase = abase + A_BYTES;

        #pragma unroll
        for (int ks = 0; ks < 4; ks++) {
            uint32_t ah[4][4], bb[8][2];
            #pragma unroll
            for (int mt = 0; mt < 4; mt++) {
                int row = wr * 64 + mt * 16 + (lane & 15);
                int kc  = ks * 2 + (lane >> 4);
                uint32_t off = row * 128 + ((kc ^ (row & 7)) << 4);
                ldsm4(abase + off, ah[mt][0], ah[mt][1], ah[mt][2], ah[mt][3]);
            }
            #pragma unroll
            for (int np = 0; np < 4; np++) {
                int n  = wc * 64 + np * 16 + ((lane >> 4) << 3) + (lane & 7);
                int kc = ks * 2 + ((lane >> 3) & 1);
                uint32_t off = n * 128 + ((kc ^ (n & 7)) << 4);
                ldsm4(bbase + off, bb[2*np][0], bb[2*np][1], bb[2*np+1][0], bb[2*np+1][1]);
            }
            #pragma unroll
            for (int mt = 0; mt < 4; mt++)
                #pragma unroll
                for (int nt = 0; nt < 8; nt++) mma_f16(acc[mt][nt], ah[mt], bb[nt]);
        }
    }

    int rowbase = blockIdx.y * 128 + wr * 64;
    int colbase = blockIdx.x * 128 + wc * 64;
    #pragma unroll
    for (int mt = 0; mt < 4; mt++) {
        #pragma unroll
        for (int nt = 0; nt < 8; nt++) {
            int m = rowbase + mt * 16 + (lane >> 2);
            int n = colbase + nt * 8 + ((lane & 3) << 1);
            float* cc = acc[mt][nt];
            #pragma unroll
            for (int half = 0; half < 2; half++) {
                size_t idx = (size_t)(m + half * 8) * N + n;
                float v0 = cc[half * 2], v1 = cc[half * 2 + 1];
                if (EPI == 0) {
                    *(__half2*)(Ch + idx) = __floats2half2_rn(v0, v1);
                } else if (EPI == 1) {
                    v0 = v0 / (1.f + expf(-v0));
                    v1 = v1 / (1.f + expf(-v1));
                    *(__half2*)(Ch + idx) = __floats2half2_rn(v0, v1);
                } else {
                    float2 r2 = *(const float2*)(resid + idx);
                    float2 o = { v0 + r2.x, v1 + r2.y };
                    *(float2*)(Cf + idx) = o;
                }
            }
        }
    }
}

// ================= single prep kernel: all weight transposes to fp16 =================
__global__ void prep_kernel(const float* __restrict__ Wq, const float* __restrict__ Wk,
                            const float* __restrict__ Wv, const float* __restrict__ Wg,
                            const float* __restrict__ Wo, const float* __restrict__ ff1,
                            const float* __restrict__ ff2,
                            __half* __restrict__ wqkvT, __half* __restrict__ woT,
                            __half* __restrict__ f1T, __half* __restrict__ f2T) {
    int id = blockIdx.x;
    int tx = threadIdx.x, ty = threadIdx.y;  // 32 x 8
    __shared__ float t[32][33];

    const float* W; __half* T; int K, N, tt, rowoff = 0;
    if (id < 64)        { W = Wq;  T = wqkvT; K = DD;  N = AD;  tt = id;        rowoff = 0; }
    else if (id < 128)  { W = Wk;  T = wqkvT; K = DD;  N = AD;  tt = id - 64;   rowoff = 64; }
    else if (id < 192)  { W = Wv;  T = wqkvT; K = DD;  N = AD;  tt = id - 128;  rowoff = 128; }
    else if (id < 256) {
        int row = id;  // 192..255: row 192 = Wg, rest zero
        int lt = ty * 32 + tx;
        for (int c = lt; c < DD; c += 256)
            wqkvT[(size_t)row * DD + c] = (row == 192) ? __float2half(Wg[c]) : __half(0.f);
        return;
    }
    else if (id < 2304) { W = ff1; T = f1T;   K = DD;  N = FFD; tt = id - 256; }
    else if (id < 4352) { W = ff2; T = f2T;   K = FFD; N = DD;  tt = id - 2304; }
    else                { W = Wo;  T = woT;   K = AD;  N = DD;  tt = id - 4352; }

    int ntiles = N / 32;
    int nb = (tt % ntiles) * 32, kb = (tt / ntiles) * 32;
    #pragma unroll
    for (int i = 0; i < 32; i += 8) t[ty + i][tx] = W[(size_t)(kb + ty + i) * N + nb + tx];
    __syncthreads();
    #pragma unroll
    for (int i = 0; i < 32; i += 8)
        T[(size_t)(rowoff + nb + ty + i) * K + kb + tx] = __float2half(t[tx][ty + i]);
}

// ---------------- warp-per-token rms + flags reset ----------------
__global__ __launch_bounds__(256) void rms_kernel(const float* __restrict__ x,
                                                  float* __restrict__ rinv,
                                                  int* __restrict__ flags) {
    if (blockIdx.x == 0 && threadIdx.x < 256) {
        flags[threadIdx.x] = 0;
        flags[threadIdx.x + 256] = 0;
    }
    int tok = blockIdx.x * 8 + (threadIdx.x >> 5);
    int lane = threadIdx.x & 31;
    const float4* xr = (const float4*)(x + (size_t)tok * DD);
    float ss = 0.f;
    #pragma unroll
    for (int i = 0; i < 8; i++) {
        float4 v = xr[lane + i * 32];
        ss += v.x*v.x + v.y*v.y + v.z*v.z + v.w*v.w;
    }
    #pragma unroll
    for (int o = 16; o > 0; o >>= 1) ss += __shfl_xor_sync(~0u, ss, o);
    if (lane == 0) rinv[tok] = rsqrtf(ss * (1.0f / DD) + EPSR);
}

// ---------------- warp-per-token rmsnorm2 ----------------
__global__ __launch_bounds__(256) void rmsnorm2_kernel(const float* __restrict__ x,
                                                       const float* __restrict__ w,
                                                       __half* __restrict__ outh) {
    int tok = blockIdx.x * 8 + (threadIdx.x >> 5);
    int lane = threadIdx.x & 31;
    const float4* xr = (const float4*)(x + (size_t)tok * DD);
    float4 xv[8];
    float ss = 0.f;
    #pragma unroll
    for (int i = 0; i < 8; i++) {
        xv[i] = xr[lane + i * 32];
        ss += xv[i].x*xv[i].x + xv[i].y*xv[i].y + xv[i].z*xv[i].z + xv[i].w*xv[i].w;
    }
    #pragma unroll
    for (int o = 16; o > 0; o >>= 1) ss += __shfl_xor_sync(~0u, ss, o);
    float r = rsqrtf(ss * (1.0f / DD) + EPSR);
    #pragma unroll
    for (int i = 0; i < 8; i++) {
        float4 wv = ((const float4*)w)[lane + i * 32];
        size_t base = (size_t)tok * DD + (lane + i * 32) * 4;
        *(__half2*)(outh + base)     = __floats2half2_rn(xv[i].x*r*wv.x, xv[i].y*r*wv.y);
        *(__half2*)(outh + base + 2) = __floats2half2_rn(xv[i].z*r*wv.z, xv[i].w*r*wv.w);
    }
}

// ---------------- fused SSM scan: decoupled lookback, single kernel ----------------
__global__ __launch_bounds__(128) void scan_fused(
    const float* __restrict__ x, const float* __restrict__ rinv,
    const float* __restrict__ n1w, const float* __restrict__ b_w,
    const float* __restrict__ a_raw, const float* __restrict__ c_w,
    float* __restrict__ agg, float* __restrict__ incl, int* __restrict__ flags,
    float* __restrict__ xssm, __half* __restrict__ xh)
{
    int blk = blockIdx.x;            // b*NCHUNK + c
    int half = blockIdx.y;
    int c = blk & (NCHUNK - 1);
    int t = threadIdx.x;
    int d4 = half * 128 + t;
    int fidx = blk * 2 + half;
    int tok0 = blk * CHUNK;

    float4 w1 = ((const float4*)n1w)[d4];
    float4 w2 = ((const float4*)b_w)[d4];
    float4 wc = { w1.x*w2.x, w1.y*w2.y, w1.z*w2.z, w1.w*w2.w };
    float4 cw = ((const float4*)c_w)[d4];
    float4 ar = ((const float4*)a_raw)[d4];
    float a0 = sigmoidf_(ar.x), a1 = sigmoidf_(ar.y), a2 = sigmoidf_(ar.z), a3 = sigmoidf_(ar.w);
    float aC0 = a0, aC1 = a1, aC2 = a2, aC3 = a3;
    #pragma unroll
    for (int i = 0; i < 6; i++) { aC0 *= aC0; aC1 *= aC1; aC2 *= aC2; aC3 *= aC3; }

    const float4* xp = (const float4*)(x + (size_t)tok0 * DD) + d4;
    const float* rp = rinv + tok0;

    float h0 = 0.f, h1 = 0.f, h2 = 0.f, h3 = 0.f;
    #pragma unroll 4
    for (int i = 0; i < CHUNK; i++) {
        float r = rp[i];
        float4 xv = xp[(size_t)i * 256];
        h0 = fmaf(a0, h0, xv.x * r * wc.x);
        h1 = fmaf(a1, h1, xv.y * r * wc.y);
        h2 = fmaf(a2, h2, xv.z * r * wc.z);
        h3 = fmaf(a3, h3, xv.w * r * wc.w);
    }

    float e0 = 0.f, e1 = 0.f, e2 = 0.f, e3 = 0.f;
    __shared__ int sflag;
    if (c == 0) {
        float4 iv = { h0, h1, h2, h3 };
        ((float4*)(incl + (size_t)blk * DD))[d4] = iv;
        __threadfence();
        __syncthreads();
        if (t == 0) atomicExch(&flags[fidx], 2);
    } else {
        float4 av = { h0, h1, h2, h3 };
        ((float4*)(agg + (size_t)blk * DD))[d4] = av;
        __threadfence();
        __syncthreads();
        if (t == 0) atomicExch(&flags[fidx], 1);
        float f0 = 1.f, f1 = 1.f, f2 = 1.f, f3 = 1.f;
        int j = blk - 1;
        while (true) {
            if (t == 0) {
                int fl;
                do { fl = atomicOr(&flags[j * 2 + half], 0); } while (fl == 0);
                sflag = fl;
            }
            __syncthreads();
            int fl = sflag;
            __threadfence();
            if (fl == 2) {
                float4 pv = ((const float4*)(incl + (size_t)j * DD))[d4];
                e0 = fmaf(f0, pv.x, e0); e1 = fmaf(f1, pv.y, e1);
                e2 = fmaf(f2, pv.z, e2); e3 = fmaf(f3, pv.w, e3);
                break;
            } else {
                float4 pv = ((const float4*)(agg + (size_t)j * DD))[d4];
                e0 = fmaf(f0, pv.x, e0); e1 = fmaf(f1, pv.y, e1);
                e2 = fmaf(f2, pv.z, e2); e3 = fmaf(f3, pv.w, e3);
                f0 *= aC0; f1 *= aC1; f2 *= aC2; f3 *= aC3;
                j--;
            }
            __syncthreads();
        }
        float4 iv = { fmaf(aC0, e0, h0), fmaf(aC1, e1, h1),
                      fmaf(aC2, e2, h2), fmaf(aC3, e3, h3) };
        ((float4*)(incl + (size_t)blk * DD))[d4] = iv;
        __threadfence();
        __syncthreads();
        if (t == 0) atomicExch(&flags[fidx], 2);
    }

    h0 = e0; h1 = e1; h2 = e2; h3 = e3;
    float4* op = (float4*)(xssm + (size_t)tok0 * DD) + d4;
    #pragma unroll 4
    for (int i = 0; i < CHUNK; i++) {
        float r = rp[i];
        float4 xv = xp[(size_t)i * 256];
        h0 = fmaf(a0, h0, xv.x * r * wc.x);
        h1 = fmaf(a1, h1, xv.y * r * wc.y);
        h2 = fmaf(a2, h2, xv.z * r * wc.z);
        h3 = fmaf(a3, h3, xv.w * r * wc.w);
        float4 v = { xv.x + h0 * cw.x, xv.y + h1 * cw.y,
                     xv.z + h2 * cw.z, xv.w + h3 * cw.w };
        op[(size_t)i * 256] = v;
        size_t ho = ((size_t)tok0 + i) * DD + (size_t)d4 * 4;
        *(__half2*)(xh + ho)     = __floats2half2_rn(v.x, v.y);
        *(__half2*)(xh + ho + 2) = __floats2half2_rn(v.z, v.w);
    }
}

// ---------------- warp-per-token sliding-window attention (fp16 QKV) ----------------
#define KV_STRIDE 66
#define ATTN_KS   0
#define ATTN_VS   25216
#define ATTN_QS   50432
#define ATTN_PS   52480
#define ATTN_SMEM 54528

__global__ __launch_bounds__(256) void attn_kernel(const __half* __restrict__ QKV,
                                                   const float* __restrict__ bias,
                                                   __half* __restrict__ ga) {
    extern __shared__ __align__(16) char smem[];
    __half* Ks = (__half*)(smem + ATTN_KS);
    __half* Vs = (__half*)(smem + ATTN_VS);
    float*  qs = (float*)(smem + ATTN_QS);
    float*  ps = (float*)(smem + ATTN_PS);

    int tok0 = blockIdx.x * 128;
    int b = tok0 / LL, l0 = tok0 % LL;
    int tid = threadIdx.x, lane = tid & 31, warp = tid >> 5;
    float gb = bias[0];

    for (int idx = tid; idx < 191 * 32; idx += 256) {
        int s = idx >> 5, dp = idx & 31;
        int r = l0 - 63 + s;
        __half2 kk = __floats2half2_rn(0.f, 0.f), vv = kk;
        if (r >= 0) {
            const __half* row = QKV + ((size_t)b * LL + r) * QKVN;
            kk = *(const __half2*)(row + 64 + dp * 2);
            vv = *(const __half2*)(row + 128 + dp * 2);
        }
        *(__half2*)(Ks + s * KV_STRIDE + dp * 2) = kk;
        *(__half2*)(Vs + s * KV_STRIDE + dp * 2) = vv;
    }
    __syncthreads();

    float* qw = qs + warp * 64;
    float* pw = ps + warp * 64;

    for (int it = 0; it < 16; it++) {
        int i = it * 8 + warp;
        int tkn = tok0 + i;
        const __half* qrow = QKV + (size_t)tkn * QKVN;
        qw[lane] = __half2float(qrow[lane]);
        qw[lane + 32] = __half2float(qrow[lane + 32]);
        float sg = 0.f;
        if (lane == 0) sg = sigmoidf_(__half2float(qrow[192]) + gb);
        sg = __shfl_sync(~0u, sg, 0);
        __syncwarp();

        int w0 = lane * 2;
        float s0 = 0.f, s1 = 0.f;
        const __half* k0 = Ks + (i + w0) * KV_STRIDE;
        const __half* k1 = k0 + KV_STRIDE;
        #pragma unroll 8
        for (int d = 0; d < AD; d += 2) {
            float q0 = qw[d], q1 = qw[d + 1];
            float2 ka = __half22float2(*(const __half2*)(k0 + d));
            float2 kb = __half22float2(*(const __half2*)(k1 + d));
            s0 = fmaf(q0, ka.x, fmaf(q1, ka.y, s0));
            s1 = fmaf(q0, kb.x, fmaf(q1, kb.y, s1));
        }
        bool v0 = (l0 + i - 63 + w0) >= 0;
        bool v1 = (l0 + i - 62 + w0) >= 0;
        s0 = v0 ? s0 * 0.125f : -INFINITY;
        s1 = v1 ? s1 * 0.125f : -INFINITY;
        float m = fmaxf(s0, s1);
        #pragma unroll
        for (int o = 16; o > 0; o >>= 1) m = fmaxf(m, __shfl_xor_sync(~0u, m, o));
        float e0 = v0 ? expf(s0 - m) : 0.f;
        float e1 = v1 ? expf(s1 - m) : 0.f;
        float sum = e0 + e1;
        #pragma unroll
        for (int o = 16; o > 0; o >>= 1) sum += __shfl_xor_sync(~0u, sum, o);
        float inv = sg / sum;
        *(float2*)(pw + w0) = make_float2(e0, e1);
        __syncwarp();

        float a0 = 0.f, a1 = 0.f;
        #pragma unroll 8
        for (int w = 0; w < WW; w++) {
            float p = pw[w];
            float2 vv = __half22float2(*(const __half2*)(Vs + (i + w) * KV_STRIDE + w0));
            a0 = fmaf(p, vv.x, a0);
            a1 = fmaf(p, vv.y, a1);
        }
        *(__half2*)(ga + (size_t)tkn * AD + w0) = __floats2half2_rn(a0 * inv, a1 * inv);
        __syncwarp();
    }
}

// ---------------- launcher ----------------
extern "C" void kernel_launch(void* const* d_in, const int* in_sizes, int n_in,
                              void* d_out, int out_size) {
    (void)in_sizes; (void)n_in; (void)out_size;
    const float* x     = (const float*)d_in[0];
    const float* n1w   = (const float*)d_in[1];
    const float* n2w   = (const float*)d_in[2];
    const float* a_raw = (const float*)d_in[3];
    const float* b_w   = (const float*)d_in[4];
    const float* c_w   = (const float*)d_in[5];
    const float* Wq    = (const float*)d_in[6];
    const float* Wk    = (const float*)d_in[7];
    const float* Wv    = (const float*)d_in[8];
    const float* Wo    = (const float*)d_in[9];
    const float* Wg    = (const float*)d_in[10];
    const float* gbias = (const float*)d_in[11];
    const float* ff1   = (const float*)d_in[12];
    const float* ff2   = (const float*)d_in[13];
    float* out = (float*)d_out;

    float *p_xssm, *p_rinv, *p_agg, *p_incl;
    int *p_flags;
    __half *p_xh, *p_n2h, *p_tmp, *p_ga, *p_qkvh, *p_wqkv, *p_woT, *p_f1T, *p_f2T;
    cudaGetSymbolAddress((void**)&p_xssm, g_xssm);
    cudaGetSymbolAddress((void**)&p_rinv, g_rinv);
    cudaGetSymbolAddress((void**)&p_agg, g_agg);
    cudaGetSymbolAddress((void**)&p_incl, g_incl);
    cudaGetSymbolAddress((void**)&p_flags, g_flags);
    cudaGetSymbolAddress((void**)&p_xh, g_xh);
    cudaGetSymbolAddress((void**)&p_n2h, g_n2h);
    cudaGetSymbolAddress((void**)&p_tmp, g_tmp);
    cudaGetSymbolAddress((void**)&p_ga, g_ga);
    cudaGetSymbolAddress((void**)&p_qkvh, g_qkvh);
    cudaGetSymbolAddress((void**)&p_wqkv, g_wqkvT);
    cudaGetSymbolAddress((void**)&p_woT, g_woT);
    cudaGetSymbolAddress((void**)&p_f1T, g_f1T);
    cudaGetSymbolAddress((void**)&p_f2T, g_f2T);

    const int SMEM_8 = 3 * (16384 + 16384);  // 98304
    const int SMEM_4 = 3 * (16384 + 16384);  // 98304
    cudaFuncSetAttribute(mma_gemm8, cudaFuncAttributeMaxDynamicSharedMemorySize, SMEM_8);
    cudaFuncSetAttribute(mma_gemm4<0>, cudaFuncAttributeMaxDynamicSharedMemorySize, SMEM_4);
    cudaFuncSetAttribute(mma_gemm4<1>, cudaFuncAttributeMaxDynamicSharedMemorySize, SMEM_4);
    cudaFuncSetAttribute(mma_gemm4<2>, cudaFuncAttributeMaxDynamicSharedMemorySize, SMEM_4);
    cudaFuncSetAttribute(attn_kernel, cudaFuncAttributeMaxDynamicSharedMemorySize, ATTN_SMEM);

    // 0) weight prep
    prep_kernel<<<4416, dim3(32, 8)>>>(Wq, Wk, Wv, Wg, Wo, ff1, ff2,
                                       p_wqkv, p_woT, p_f1T, p_f2T);
    // 1) per-token rms of x + flag reset
    rms_kernel<<<MROWS / 8, 256>>>(x, p_rinv, p_flags);
    // 2) fused decoupled-lookback SSM scan
    scan_fused<<<dim3(BB * NCHUNK, 2), 128>>>(x, p_rinv, n1w, b_w, a_raw, c_w,
                                              p_agg, p_incl, p_flags, p_xssm, p_xh);
    // 3) fused QKV+gate projection -> fp16 (4-warp crossbar-optimal)
    {
        dim3 grid(QKVN / 128, MROWS / 128);
        mma_gemm4<0><<<grid, 128, SMEM_4>>>(QKVN, DD, p_xh, p_wqkv, nullptr, p_qkvh, nullptr);
    }
    // 4) attention + gate -> ga fp16
    attn_kernel<<<MROWS / 128, 256, ATTN_SMEM>>>(p_qkvh, gbias, p_ga);
    // 5) x_ssm += ga @ WoT (8-warp, memory-bound K=64)
    {
        dim3 grid(DD / 128, MROWS / 128);
        mma_gemm8<<<grid, 256, SMEM_8>>>(DD, AD, p_ga, p_woT, p_xssm, p_xssm);
    }
    // 6) n2 = rmsnorm(x_ssm)*n2w -> fp16
    rmsnorm2_kernel<<<MROWS / 8, 256>>>(p_xssm, n2w, p_n2h);
    // 7) tmp = silu(n2 @ ff_w1) -> fp16 (4-warp crossbar-optimal)
    {
        dim3 grid(FFD / 128, MROWS / 128);
        mma_gemm4<1><<<grid, 128, SMEM_4>>>(FFD, DD, p_n2h, p_f1T, nullptr, p_tmp, nullptr);
    }
    // 8) out = x_ssm + tmp @ ff_w2 (4-warp crossbar-optimal)
    {
        dim3 grid(DD / 128, MROWS / 128);
        mma_gemm4<2><<<grid, 128, SMEM_4>>>(DD, FFD, p_tmp, p_f2T, out, nullptr, p_xssm);
    }
}

// round 15
// speedup vs baseline: 1.0433x; 1.0433x over previous
#include <cuda_runtime.h>
#include <cuda_fp16.h>
#include <cstdint>
#include <math.h>

// ---------------- problem constants ----------------
#define BB     4
#define LL     4096
#define DD     1024
#define AD     64
#define WW     64
#define FFD    2048
#define MROWS  (BB*LL)
#define CHUNK  64
#define NCHUNK (LL/CHUNK)
#define EPSR   1e-6f
#define QKVN   256         // q|k|v|gate padded width

// ---------------- scratch ----------------
__device__ float  g_xssm[(size_t)MROWS*DD];
__device__ float  g_rinv[MROWS];
__device__ __half g_xh[(size_t)MROWS*DD];
__device__ __half g_n2h[(size_t)MROWS*DD];
__device__ __half g_tmp[(size_t)MROWS*FFD];
__device__ __half g_ga[(size_t)MROWS*AD];
__device__ float  g_agg[(size_t)BB*NCHUNK*DD];
__device__ float  g_incl[(size_t)BB*NCHUNK*DD];
__device__ int    g_flags[BB*NCHUNK*2];
__device__ __half g_qkvh[(size_t)MROWS*QKVN];
__device__ __half g_wqkvT[(size_t)QKVN*DD];
__device__ __half g_woT[(size_t)DD*AD];
__device__ __half g_f1T[(size_t)FFD*DD];
__device__ __half g_f2T[(size_t)DD*FFD];

__device__ __forceinline__ float sigmoidf_(float x) { return 1.0f / (1.0f + expf(-x)); }

__device__ __forceinline__ uint32_t smem_u32(const void* p) {
    uint32_t a;
    asm("{ .reg .u64 t; cvta.to.shared.u64 t, %1; cvt.u32.u64 %0, t; }" : "=r"(a) : "l"(p));
    return a;
}
__device__ __forceinline__ void cp16(uint32_t dst, const void* src) {
    asm volatile("cp.async.cg.shared.global [%0], [%1], 16;" :: "r"(dst), "l"(src));
}
__device__ __forceinline__ void cp_commit() { asm volatile("cp.async.commit_group;"); }
template <int N> __device__ __forceinline__ void cp_wait() {
    asm volatile("cp.async.wait_group %0;" :: "n"(N) : "memory");
}
__device__ __forceinline__ void ldsm4(uint32_t addr, uint32_t& r0, uint32_t& r1,
                                      uint32_t& r2, uint32_t& r3) {
    asm volatile("ldmatrix.sync.aligned.m8n8.x4.shared.b16 {%0,%1,%2,%3}, [%4];"
                 : "=r"(r0), "=r"(r1), "=r"(r2), "=r"(r3) : "r"(addr));
}
__device__ __forceinline__ void mma_f16(float* c, const uint32_t* a, const uint32_t* b) {
    asm volatile("mma.sync.aligned.m16n8k16.row.col.f32.f16.f16.f32 "
                 "{%0,%1,%2,%3}, {%4,%5,%6,%7}, {%8,%9}, {%0,%1,%2,%3};"
                 : "+f"(c[0]), "+f"(c[1]), "+f"(c[2]), "+f"(c[3])
                 : "r"(a[0]), "r"(a[1]), "r"(a[2]), "r"(a[3]), "r"(b[0]), "r"(b[1]));
}

// ====== GEMM-A: 8 warps (4x2), BM=128, BN=128, BK=64. For Wo + FF (best measured). ======
// EPI: 1 = silu + fp16 C; 2 = +resid fp32 C
template <int EPI>
__global__ __launch_bounds__(256, 2) void mma_gemm8(
    int N, int K,
    const __half* __restrict__ A, const __half* __restrict__ B,
    float* __restrict__ Cf, __half* __restrict__ Ch,
    const float* __restrict__ resid)
{
    constexpr int BN = 128;
    constexpr int NT = BN / 16;
    constexpr int A_BYTES = 128 * 128;
    constexpr int B_BYTES = BN * 128;
    constexpr int STAGE = A_BYTES + B_BYTES;

    extern __shared__ __align__(128) char smem[];
    uint32_t sb = smem_u32(smem);

    const int tid  = threadIdx.x;
    const int lane = tid & 31;
    const int wid  = tid >> 5;
    const int wr   = wid & 3;
    const int wc   = wid >> 2;

    const __half* Ab = A + (size_t)blockIdx.y * 128 * K;
    const __half* Bb = B + (size_t)blockIdx.x * BN * K;

    const int NIT = K >> 6;

    auto load_stage = [&](int s, int kb) {
        uint32_t base = sb + s * STAGE;
        const __half* g = Ab + kb;
        #pragma unroll
        for (int i = tid; i < 1024; i += 256) {
            int r = i >> 3, kc = i & 7;
            cp16(base + r * 128 + ((kc ^ (r & 7)) << 4), g + (size_t)r * K + kc * 8);
        }
        g = Bb + kb;
        uint32_t bdst = base + A_BYTES;
        #pragma unroll
        for (int i = tid; i < BN * 8; i += 256) {
            int r = i >> 3, kc = i & 7;
            cp16(bdst + r * 128 + ((kc ^ (r & 7)) << 4), g + (size_t)r * K + kc * 8);
        }
    };

    auto ld_afrag = [&](uint32_t abase, int ks, uint32_t af[2][4]) {
        #pragma unroll
        for (int mt = 0; mt < 2; mt++) {
            int row = wr * 32 + mt * 16 + (lane & 15);
            int kc  = ks * 2 + (lane >> 4);
            uint32_t off = row * 128 + ((kc ^ (row & 7)) << 4);
            ldsm4(abase + off, af[mt][0], af[mt][1], af[mt][2], af[mt][3]);
        }
    };
    auto ld_bfrag = [&](uint32_t bbase, int ks, uint32_t bf[NT][2]) {
        #pragma unroll
        for (int np = 0; np < NT / 2; np++) {
            int n  = wc * (BN / 2) + np * 16 + ((lane >> 4) << 3) + (lane & 7);
            int kc = ks * 2 + ((lane >> 3) & 1);
            uint32_t off = n * 128 + ((kc ^ (n & 7)) << 4);
            ldsm4(bbase + off, bf[2*np][0], bf[2*np][1], bf[2*np+1][0], bf[2*np+1][1]);
        }
    };

    float acc[2][NT][4];
    #pragma unroll
    for (int mt = 0; mt < 2; mt++)
        #pragma unroll
        for (int nt = 0; nt < NT; nt++)
            #pragma unroll
            for (int j = 0; j < 4; j++) acc[mt][nt][j] = 0.f;

    load_stage(0, 0);
    cp_commit();
    if (NIT > 1) { load_stage(1, 64); cp_commit(); }

    for (int it = 0; it < NIT; it++) {
        if (it + 1 < NIT) cp_wait<1>(); else cp_wait<0>();
        __syncthreads();
        if (it + 2 < NIT) {
            load_stage((it + 2) % 3, (it + 2) << 6);
            cp_commit();
        }

        uint32_t abase = sb + (it % 3) * STAGE;
        uint32_t bbase = abase + A_BYTES;

        uint32_t ah[2][2][4], bbf[NT][2];
        ld_afrag(abase, 0, ah[0]);
        #pragma unroll
        for (int ks = 0; ks < 4; ks++) {
            int cur = ks & 1, nxt = cur ^ 1;
            ld_bfrag(bbase, ks, bbf);
            if (ks < 3) ld_afrag(abase, ks + 1, ah[nxt]);
            #pragma unroll
            for (int mt = 0; mt < 2; mt++)
                #pragma unroll
                for (int nt = 0; nt < NT; nt++) mma_f16(acc[mt][nt], ah[cur][mt], bbf[nt]);
        }
    }

    int rowbase = blockIdx.y * 128 + wr * 32;
    int colbase = blockIdx.x * BN + wc * (BN / 2);
    #pragma unroll
    for (int mt = 0; mt < 2; mt++) {
        #pragma unroll
        for (int nt = 0; nt < NT; nt++) {
            int m = rowbase + mt * 16 + (lane >> 2);
            int n = colbase + nt * 8 + ((lane & 3) << 1);
            float* cc = acc[mt][nt];
            #pragma unroll
            for (int half = 0; half < 2; half++) {
                size_t idx = (size_t)(m + half * 8) * N + n;
                float v0 = cc[half * 2], v1 = cc[half * 2 + 1];
                if (EPI == 1) {
                    v0 = v0 / (1.f + expf(-v0));
                    v1 = v1 / (1.f + expf(-v1));
                    *(__half2*)(Ch + idx) = __floats2half2_rn(v0, v1);
                } else {
                    float2 r2 = *(const float2*)(resid + idx);
                    float2 o = { v0 + r2.x, v1 + r2.y };
                    *(float2*)(Cf + idx) = o;
                }
            }
        }
    }
}

// ====== GEMM-B: 4 warps (2x2), BM=BN=128, warp 64x64 (crossbar-optimal). QKV only. ======
__global__ __launch_bounds__(128, 2) void mma_gemm4(
    int N, int K,
    const __half* __restrict__ A, const __half* __restrict__ B,
    __half* __restrict__ Ch)
{
    constexpr int A_BYTES = 128 * 128;
    constexpr int STAGE = 2 * A_BYTES;   // 32 KB

    extern __shared__ __align__(128) char smem[];
    uint32_t sb = smem_u32(smem);

    const int tid  = threadIdx.x;
    const int lane = tid & 31;
    const int wid  = tid >> 5;
    const int wr   = wid & 1;
    const int wc   = wid >> 1;

    const __half* Ab = A + (size_t)blockIdx.y * 128 * K;
    const __half* Bb = B + (size_t)blockIdx.x * 128 * K;

    const int NIT = K >> 6;

    auto load_stage = [&](int s, int kb) {
        uint32_t base = sb + s * STAGE;
        const __half* g = Ab + kb;
        #pragma unroll
        for (int i = tid; i < 1024; i += 128) {
            int r = i >> 3, kc = i & 7;
            cp16(base + r * 128 + ((kc ^ (r & 7)) << 4), g + (size_t)r * K + kc * 8);
        }
        g = Bb + kb;
        uint32_t bdst = base + A_BYTES;
        #pragma unroll
        for (int i = tid; i < 1024; i += 128) {
            int r = i >> 3, kc = i & 7;
            cp16(bdst + r * 128 + ((kc ^ (r & 7)) << 4), g + (size_t)r * K + kc * 8);
        }
    };

    float acc[4][8][4];
    #pragma unroll
    for (int mt = 0; mt < 4; mt++)
        #pragma unroll
        for (int nt = 0; nt < 8; nt++)
            #pragma unroll
            for (int j = 0; j < 4; j++) acc[mt][nt][j] = 0.f;

    load_stage(0, 0);
    cp_commit();
    if (NIT > 1) { load_stage(1, 64); cp_commit(); }

    for (int it = 0; it < NIT; it++) {
        if (it + 1 < NIT) cp_wait<1>(); else cp_wait<0>();
        __syncthreads();
        if (it + 2 < NIT) {
            load_stage((it + 2) % 3, (it + 2) << 6);
            cp_commit();
        }

        uint32_t abase = sb + (it % 3) * STAGE;
        uint32_t bbase = abase + A_BYTES;

        #pragma unroll
        for (int ks = 0; ks < 4; ks++) {
            uint32_t ah[4][4], bb[8][2];
            #pragma unroll
            for (int mt = 0; mt < 4; mt++) {
                int row = wr * 64 + mt * 16 + (lane & 15);
                int kc  = ks * 2 + (lane >> 4);
                uint32_t off = row * 128 + ((kc ^ (row & 7)) << 4);
                ldsm4(abase + off, ah[mt][0], ah[mt][1], ah[mt][2], ah[mt][3]);
            }
            #pragma unroll
            for (int np = 0; np < 4; np++) {
                int n  = wc * 64 + np * 16 + ((lane >> 4) << 3) + (lane & 7);
                int kc = ks * 2 + ((lane >> 3) & 1);
                uint32_t off = n * 128 + ((kc ^ (n & 7)) << 4);
                ldsm4(bbase + off, bb[2*np][0], bb[2*np][1], bb[2*np+1][0], bb[2*np+1][1]);
            }
            #pragma unroll
            for (int mt = 0; mt < 4; mt++)
                #pragma unroll
                for (int nt = 0; nt < 8; nt++) mma_f16(acc[mt][nt], ah[mt], bb[nt]);
        }
    }

    int rowbase = blockIdx.y * 128 + wr * 64;
    int colbase = blockIdx.x * 128 + wc * 64;
    #pragma unroll
    for (int mt = 0; mt < 4; mt++) {
        #pragma unroll
        for (int nt = 0; nt < 8; nt++) {
            int m = rowbase + mt * 16 + (lane >> 2);
            int n = colbase + nt * 8 + ((lane & 3) << 1);
            float* cc = acc[mt][nt];
            #pragma unroll
            for (int half = 0; half < 2; half++) {
                size_t idx = (size_t)(m + half * 8) * N + n;
                *(__half2*)(Ch + idx) = __floats2half2_rn(cc[half * 2], cc[half * 2 + 1]);
            }
        }
    }
}

// ================= single prep kernel: all weight transposes to fp16 =================
__global__ void prep_kernel(const float* __restrict__ Wq, const float* __restrict__ Wk,
                            const float* __restrict__ Wv, const float* __restrict__ Wg,
                            const float* __restrict__ Wo, const float* __restrict__ ff1,
                            const float* __restrict__ ff2,
                            __half* __restrict__ wqkvT, __half* __restrict__ woT,
                            __half* __restrict__ f1T, __half* __restrict__ f2T) {
    int id = blockIdx.x;
    int tx = threadIdx.x, ty = threadIdx.y;  // 32 x 8
    __shared__ float t[32][33];

    const float* W; __half* T; int K, N, tt, rowoff = 0;
    if (id < 64)        { W = Wq;  T = wqkvT; K = DD;  N = AD;  tt = id;        rowoff = 0; }
    else if (id < 128)  { W = Wk;  T = wqkvT; K = DD;  N = AD;  tt = id - 64;   rowoff = 64; }
    else if (id < 192)  { W = Wv;  T = wqkvT; K = DD;  N = AD;  tt = id - 128;  rowoff = 128; }
    else if (id < 256) {
        int row = id;  // 192..255: row 192 = Wg, rest zero
        int lt = ty * 32 + tx;
        for (int c = lt; c < DD; c += 256)
            wqkvT[(size_t)row * DD + c] = (row == 192) ? __float2half(Wg[c]) : __half(0.f);
        return;
    }
    else if (id < 2304) { W = ff1; T = f1T;   K = DD;  N = FFD; tt = id - 256; }
    else if (id < 4352) { W = ff2; T = f2T;   K = FFD; N = DD;  tt = id - 2304; }
    else                { W = Wo;  T = woT;   K = AD;  N = DD;  tt = id - 4352; }

    int ntiles = N / 32;
    int nb = (tt % ntiles) * 32, kb = (tt / ntiles) * 32;
    #pragma unroll
    for (int i = 0; i < 32; i += 8) t[ty + i][tx] = W[(size_t)(kb + ty + i) * N + nb + tx];
    __syncthreads();
    #pragma unroll
    for (int i = 0; i < 32; i += 8)
        T[(size_t)(rowoff + nb + ty + i) * K + kb + tx] = __float2half(t[tx][ty + i]);
}

// ---------------- warp-per-token rms + flags reset ----------------
__global__ __launch_bounds__(256) void rms_kernel(const float* __restrict__ x,
                                                  float* __restrict__ rinv,
                                                  int* __restrict__ flags) {
    if (blockIdx.x == 0 && threadIdx.x < 256) {
        flags[threadIdx.x] = 0;
        flags[threadIdx.x + 256] = 0;
    }
    int tok = blockIdx.x * 8 + (threadIdx.x >> 5);
    int lane = threadIdx.x & 31;
    const float4* xr = (const float4*)(x + (size_t)tok * DD);
    float ss = 0.f;
    #pragma unroll
    for (int i = 0; i < 8; i++) {
        float4 v = xr[lane + i * 32];
        ss += v.x*v.x + v.y*v.y + v.z*v.z + v.w*v.w;
    }
    #pragma unroll
    for (int o = 16; o > 0; o >>= 1) ss += __shfl_xor_sync(~0u, ss, o);
    if (lane == 0) rinv[tok] = rsqrtf(ss * (1.0f / DD) + EPSR);
}

// ---------------- warp-per-token rmsnorm2 ----------------
__global__ __launch_bounds__(256) void rmsnorm2_kernel(const float* __restrict__ x,
                                                       const float* __restrict__ w,
                                                       __half* __restrict__ outh) {
    int tok = blockIdx.x * 8 + (threadIdx.x >> 5);
    int lane = threadIdx.x & 31;
    const float4* xr = (const float4*)(x + (size_t)tok * DD);
    float4 xv[8];
    float ss = 0.f;
    #pragma unroll
    for (int i = 0; i < 8; i++) {
        xv[i] = xr[lane + i * 32];
        ss += xv[i].x*xv[i].x + xv[i].y*xv[i].y + xv[i].z*xv[i].z + xv[i].w*xv[i].w;
    }
    #pragma unroll
    for (int o = 16; o > 0; o >>= 1) ss += __shfl_xor_sync(~0u, ss, o);
    float r = rsqrtf(ss * (1.0f / DD) + EPSR);
    #pragma unroll
    for (int i = 0; i < 8; i++) {
        float4 wv = ((const float4*)w)[lane + i * 32];
        size_t base = (size_t)tok * DD + (lane + i * 32) * 4;
        *(__half2*)(outh + base)     = __floats2half2_rn(xv[i].x*r*wv.x, xv[i].y*r*wv.y);
        *(__half2*)(outh + base + 2) = __floats2half2_rn(xv[i].z*r*wv.z, xv[i].w*r*wv.w);
    }
}

// ---------------- fused SSM scan: decoupled lookback, single kernel ----------------
__global__ __launch_bounds__(128) void scan_fused(
    const float* __restrict__ x, const float* __restrict__ rinv,
    const float* __restrict__ n1w, const float* __restrict__ b_w,
    const float* __restrict__ a_raw, const float* __restrict__ c_w,
    float* __restrict__ agg, float* __restrict__ incl, int* __restrict__ flags,
    float* __restrict__ xssm, __half* __restrict__ xh)
{
    int blk = blockIdx.x;            // b*NCHUNK + c
    int half = blockIdx.y;
    int c = blk & (NCHUNK - 1);
    int t = threadIdx.x;
    int d4 = half * 128 + t;
    int fidx = blk * 2 + half;
    int tok0 = blk * CHUNK;

    float4 w1 = ((const float4*)n1w)[d4];
    float4 w2 = ((const float4*)b_w)[d4];
    float4 wc = { w1.x*w2.x, w1.y*w2.y, w1.z*w2.z, w1.w*w2.w };
    float4 cw = ((const float4*)c_w)[d4];
    float4 ar = ((const float4*)a_raw)[d4];
    float a0 = sigmoidf_(ar.x), a1 = sigmoidf_(ar.y), a2 = sigmoidf_(ar.z), a3 = sigmoidf_(ar.w);
    float aC0 = a0, aC1 = a1, aC2 = a2, aC3 = a3;
    #pragma unroll
    for (int i = 0; i < 6; i++) { aC0 *= aC0; aC1 *= aC1; aC2 *= aC2; aC3 *= aC3; }

    const float4* xp = (const float4*)(x + (size_t)tok0 * DD) + d4;
    const float* rp = rinv + tok0;

    float h0 = 0.f, h1 = 0.f, h2 = 0.f, h3 = 0.f;
    #pragma unroll 4
    for (int i = 0; i < CHUNK; i++) {
        float r = rp[i];
        float4 xv = xp[(size_t)i * 256];
        h0 = fmaf(a0, h0, xv.x * r * wc.x);
        h1 = fmaf(a1, h1, xv.y * r * wc.y);
        h2 = fmaf(a2, h2, xv.z * r * wc.z);
        h3 = fmaf(a3, h3, xv.w * r * wc.w);
    }

    float e0 = 0.f, e1 = 0.f, e2 = 0.f, e3 = 0.f;
    __shared__ int sflag;
    if (c == 0) {
        float4 iv = { h0, h1, h2, h3 };
        ((float4*)(incl + (size_t)blk * DD))[d4] = iv;
        __threadfence();
        __syncthreads();
        if (t == 0) atomicExch(&flags[fidx], 2);
    } else {
        float4 av = { h0, h1, h2, h3 };
        ((float4*)(agg + (size_t)blk * DD))[d4] = av;
        __threadfence();
        __syncthreads();
        if (t == 0) atomicExch(&flags[fidx], 1);
        float f0 = 1.f, f1 = 1.f, f2 = 1.f, f3 = 1.f;
        int j = blk - 1;
        while (true) {
            if (t == 0) {
                int fl;
                do { fl = atomicOr(&flags[j * 2 + half], 0); } while (fl == 0);
                sflag = fl;
            }
            __syncthreads();
            int fl = sflag;
            __threadfence();
            if (fl == 2) {
                float4 pv = ((const float4*)(incl + (size_t)j * DD))[d4];
                e0 = fmaf(f0, pv.x, e0); e1 = fmaf(f1, pv.y, e1);
                e2 = fmaf(f2, pv.z, e2); e3 = fmaf(f3, pv.w, e3);
                break;
            } else {
                float4 pv = ((const float4*)(agg + (size_t)j * DD))[d4];
                e0 = fmaf(f0, pv.x, e0); e1 = fmaf(f1, pv.y, e1);
                e2 = fmaf(f2, pv.z, e2); e3 = fmaf(f3, pv.w, e3);
                f0 *= aC0; f1 *= aC1; f2 *= aC2; f3 *= aC3;
                j--;
            }
            __syncthreads();
        }
        float4 iv = { fmaf(aC0, e0, h0), fmaf(aC1, e1, h1),
                      fmaf(aC2, e2, h2), fmaf(aC3, e3, h3) };
        ((float4*)(incl + (size_t)blk * DD))[d4] = iv;
        __threadfence();
        __syncthreads();
        if (t == 0) atomicExch(&flags[fidx], 2);
    }

    h0 = e0; h1 = e1; h2 = e2; h3 = e3;
    float4* op = (float4*)(xssm + (size_t)tok0 * DD) + d4;
    #pragma unroll 4
    for (int i = 0; i < CHUNK; i++) {
        float r = rp[i];
        float4 xv = xp[(size_t)i * 256];
        h0 = fmaf(a0, h0, xv.x * r * wc.x);
        h1 = fmaf(a1, h1, xv.y * r * wc.y);
        h2 = fmaf(a2, h2, xv.z * r * wc.z);
        h3 = fmaf(a3, h3, xv.w * r * wc.w);
        float4 v = { xv.x + h0 * cw.x, xv.y + h1 * cw.y,
                     xv.z + h2 * cw.z, xv.w + h3 * cw.w };
        op[(size_t)i * 256] = v;
        size_t ho = ((size_t)tok0 + i) * DD + (size_t)d4 * 4;
        *(__half2*)(xh + ho)     = __floats2half2_rn(v.x, v.y);
        *(__half2*)(xh + ho + 2) = __floats2half2_rn(v.z, v.w);
    }
}

// ---------------- warp-per-token sliding-window attention: 64 tokens/block ----------------
// K/V window rows [l0-63, l0+63] = 127 rows staged fp16 (stride 66). 8 warps, 8 iters.
#define KV_STRIDE 66
#define ATTN_KS   0
#define ATTN_VS   16768
#define ATTN_QS   33536   // 8 warps * 64 fp32
#define ATTN_PS   35584   // 8 warps * 64 fp32
#define ATTN_SMEM 37632

__global__ __launch_bounds__(256) void attn_kernel(const __half* __restrict__ QKV,
                                                   const float* __restrict__ bias,
                                                   __half* __restrict__ ga) {
    extern __shared__ __align__(16) char smem[];
    __half* Ks = (__half*)(smem + ATTN_KS);
    __half* Vs = (__half*)(smem + ATTN_VS);
    float*  qs = (float*)(smem + ATTN_QS);
    float*  ps = (float*)(smem + ATTN_PS);

    int tok0 = blockIdx.x * 64;
    int b = tok0 / LL, l0 = tok0 % LL;
    int tid = threadIdx.x, lane = tid & 31, warp = tid >> 5;
    float gb = bias[0];

    // stage K/V rows [l0-63, l0+63] -> smem rows 0..126
    for (int idx = tid; idx < 127 * 32; idx += 256) {
        int s = idx >> 5, dp = idx & 31;
        int r = l0 - 63 + s;
        __half2 kk = __floats2half2_rn(0.f, 0.f), vv = kk;
        if (r >= 0) {
            const __half* row = QKV + ((size_t)b * LL + r) * QKVN;
            kk = *(const __half2*)(row + 64 + dp * 2);
            vv = *(const __half2*)(row + 128 + dp * 2);
        }
        *(__half2*)(Ks + s * KV_STRIDE + dp * 2) = kk;
        *(__half2*)(Vs + s * KV_STRIDE + dp * 2) = vv;
    }
    __syncthreads();

    float* qw = qs + warp * 64;
    float* pw = ps + warp * 64;

    for (int it = 0; it < 8; it++) {
        int i = it * 8 + warp;           // token offset in block (0..63)
        int tkn = tok0 + i;
        const __half* qrow = QKV + (size_t)tkn * QKVN;
        qw[lane] = __half2float(qrow[lane]);
        qw[lane + 32] = __half2float(qrow[lane + 32]);
        float sg = 0.f;
        if (lane == 0) sg = sigmoidf_(__half2float(qrow[192]) + gb);
        sg = __shfl_sync(~0u, sg, 0);
        __syncwarp();

        int w0 = lane * 2;
        float s0 = 0.f, s1 = 0.f;
        const __half* k0 = Ks + (i + w0) * KV_STRIDE;
        const __half* k1 = k0 + KV_STRIDE;
        #pragma unroll 8
        for (int d = 0; d < AD; d += 2) {
            float q0 = qw[d], q1 = qw[d + 1];
            float2 ka = __half22float2(*(const __half2*)(k0 + d));
            float2 kb = __half22float2(*(const __half2*)(k1 + d));
            s0 = fmaf(q0, ka.x, fmaf(q1, ka.y, s0));
            s1 = fmaf(q0, kb.x, fmaf(q1, kb.y, s1));
        }
        bool v0 = (l0 + i - 63 + w0) >= 0;
        bool v1 = (l0 + i - 62 + w0) >= 0;
        s0 = v0 ? s0 * 0.125f : -INFINITY;
        s1 = v1 ? s1 * 0.125f : -INFINITY;
        float m = fmaxf(s0, s1);
        #pragma unroll
        for (int o = 16; o > 0; o >>= 1) m = fmaxf(m, __shfl_xor_sync(~0u, m, o));
        float e0 = v0 ? expf(s0 - m) : 0.f;
        float e1 = v1 ? expf(s1 - m) : 0.f;
        float sum = e0 + e1;
        #pragma unroll
        for (int o = 16; o > 0; o >>= 1) sum += __shfl_xor_sync(~0u, sum, o);
        float inv = sg / sum;
        *(float2*)(pw + w0) = make_float2(e0, e1);
        __syncwarp();

        float a0 = 0.f, a1 = 0.f;
        #pragma unroll 8
        for (int w = 0; w < WW; w++) {
            float p = pw[w];
            float2 vv = __half22float2(*(const __half2*)(Vs + (i + w) * KV_STRIDE + w0));
            a0 = fmaf(p, vv.x, a0);
            a1 = fmaf(p, vv.y, a1);
        }
        *(__half2*)(ga + (size_t)tkn * AD + w0) = __floats2half2_rn(a0 * inv, a1 * inv);
        __syncwarp();
    }
}

// ---------------- launcher ----------------
extern "C" void kernel_launch(void* const* d_in, const int* in_sizes, int n_in,
                              void* d_out, int out_size) {
    (void)in_sizes; (void)n_in; (void)out_size;
    const float* x     = (const float*)d_in[0];
    const float* n1w   = (const float*)d_in[1];
    const float* n2w   = (const float*)d_in[2];
    const float* a_raw = (const float*)d_in[3];
    const float* b_w   = (const float*)d_in[4];
    const float* c_w   = (const float*)d_in[5];
    const float* Wq    = (const float*)d_in[6];
    const float* Wk    = (const float*)d_in[7];
    const float* Wv    = (const float*)d_in[8];
    const float* Wo    = (const float*)d_in[9];
    const float* Wg    = (const float*)d_in[10];
    const float* gbias = (const float*)d_in[11];
    const float* ff1   = (const float*)d_in[12];
    const float* ff2   = (const float*)d_in[13];
    float* out = (float*)d_out;

    float *p_xssm, *p_rinv, *p_agg, *p_incl;
    int *p_flags;
    __half *p_xh, *p_n2h, *p_tmp, *p_ga, *p_qkvh, *p_wqkv, *p_woT, *p_f1T, *p_f2T;
    cudaGetSymbolAddress((void**)&p_xssm, g_xssm);
    cudaGetSymbolAddress((void**)&p_rinv, g_rinv);
    cudaGetSymbolAddress((void**)&p_agg, g_agg);
    cudaGetSymbolAddress((void**)&p_incl, g_incl);
    cudaGetSymbolAddress((void**)&p_flags, g_flags);
    cudaGetSymbolAddress((void**)&p_xh, g_xh);
    cudaGetSymbolAddress((void**)&p_n2h, g_n2h);
    cudaGetSymbolAddress((void**)&p_tmp, g_tmp);
    cudaGetSymbolAddress((void**)&p_ga, g_ga);
    cudaGetSymbolAddress((void**)&p_qkvh, g_qkvh);
    cudaGetSymbolAddress((void**)&p_wqkv, g_wqkvT);
    cudaGetSymbolAddress((void**)&p_woT, g_woT);
    cudaGetSymbolAddress((void**)&p_f1T, g_f1T);
    cudaGetSymbolAddress((void**)&p_f2T, g_f2T);

    const int SMEM_8 = 3 * (16384 + 16384);  // 98304
    const int SMEM_4 = 3 * (16384 + 16384);  // 98304
    cudaFuncSetAttribute(mma_gemm8<1>, cudaFuncAttributeMaxDynamicSharedMemorySize, SMEM_8);
    cudaFuncSetAttribute(mma_gemm8<2>, cudaFuncAttributeMaxDynamicSharedMemorySize, SMEM_8);
    cudaFuncSetAttribute(mma_gemm4, cudaFuncAttributeMaxDynamicSharedMemorySize, SMEM_4);
    cudaFuncSetAttribute(attn_kernel, cudaFuncAttributeMaxDynamicSharedMemorySize, ATTN_SMEM);

    // 0) weight prep
    prep_kernel<<<4416, dim3(32, 8)>>>(Wq, Wk, Wv, Wg, Wo, ff1, ff2,
                                       p_wqkv, p_woT, p_f1T, p_f2T);
    // 1) per-token rms of x + flag reset
    rms_kernel<<<MROWS / 8, 256>>>(x, p_rinv, p_flags);
    // 2) fused decoupled-lookback SSM scan
    scan_fused<<<dim3(BB * NCHUNK, 2), 128>>>(x, p_rinv, n1w, b_w, a_raw, c_w,
                                              p_agg, p_incl, p_flags, p_xssm, p_xh);
    // 3) fused QKV+gate projection -> fp16 (4-warp crossbar-optimal)
    {
        dim3 grid(QKVN / 128, MROWS / 128);
        mma_gemm4<<<grid, 128, SMEM_4>>>(QKVN, DD, p_xh, p_wqkv, p_qkvh);
    }
    // 4) attention + gate -> ga fp16 (64 tokens/block, 256 blocks)
    attn_kernel<<<MROWS / 64, 256, ATTN_SMEM>>>(p_qkvh, gbias, p_ga);
    // 5) x_ssm += ga @ WoT (8-warp)
    {
        dim3 grid(DD / 128, MROWS / 128);
        mma_gemm8<2><<<grid, 256, SMEM_8>>>(DD, AD, p_ga, p_woT, p_xssm, nullptr, p_xssm);
    }
    // 6) n2 = rmsnorm(x_ssm)*n2w -> fp16
    rmsnorm2_kernel<<<MROWS / 8, 256>>>(p_xssm, n2w, p_n2h);
    // 7) tmp = silu(n2 @ ff_w1) -> fp16 (8-warp)
    {
        dim3 grid(FFD / 128, MROWS / 128);
        mma_gemm8<1><<<grid, 256, SMEM_8>>>(FFD, DD, p_n2h, p_f1T, nullptr, p_tmp, nullptr);
    }
    // 8) out = x_ssm + tmp @ ff_w2 (8-warp)
    {
        dim3 grid(DD / 128, MROWS / 128);
        mma_gemm8<2><<<grid, 256, SMEM_8>>>(DD, FFD, p_tmp, p_f2T, out, nullptr, p_xssm);
    }
}

// round 16
// speedup vs baseline: 1.0741x; 1.0296x over previous
#include <cuda_runtime.h>
#include <cuda_fp16.h>
#include <cstdint>
#include <math.h>

// ---------------- problem constants ----------------
#define BB     4
#define LL     4096
#define DD     1024
#define AD     64
#define WW     64
#define FFD    2048
#define MROWS  (BB*LL)
#define CHUNK  64
#define NCHUNK (LL/CHUNK)
#define EPSR   1e-6f
#define QKVN   256         // q|k|v|gate padded width

// ---------------- scratch ----------------
__device__ float  g_rinv[MROWS];
__device__ __half g_xh[(size_t)MROWS*DD];        // fp16 x_ssm (residual stream)
__device__ __half g_n2h[(size_t)MROWS*DD];
__device__ __half g_tmp[(size_t)MROWS*FFD];
__device__ __half g_ga[(size_t)MROWS*AD];
__device__ float  g_agg[(size_t)BB*NCHUNK*DD];
__device__ float  g_incl[(size_t)BB*NCHUNK*DD];
__device__ int    g_flags[BB*NCHUNK*2];
__device__ __half g_qkvh[(size_t)MROWS*QKVN];
__device__ __half g_wqkvT[(size_t)QKVN*DD];
__device__ __half g_woT[(size_t)DD*AD];
__device__ __half g_f1T[(size_t)FFD*DD];
__device__ __half g_f2T[(size_t)DD*FFD];

__device__ __forceinline__ float sigmoidf_(float x) { return 1.0f / (1.0f + expf(-x)); }

__device__ __forceinline__ uint32_t smem_u32(const void* p) {
    uint32_t a;
    asm("{ .reg .u64 t; cvta.to.shared.u64 t, %1; cvt.u32.u64 %0, t; }" : "=r"(a) : "l"(p));
    return a;
}
__device__ __forceinline__ void cp16(uint32_t dst, const void* src) {
    asm volatile("cp.async.cg.shared.global [%0], [%1], 16;" :: "r"(dst), "l"(src));
}
__device__ __forceinline__ void cp_commit() { asm volatile("cp.async.commit_group;"); }
template <int N> __device__ __forceinline__ void cp_wait() {
    asm volatile("cp.async.wait_group %0;" :: "n"(N) : "memory");
}
__device__ __forceinline__ void ldsm4(uint32_t addr, uint32_t& r0, uint32_t& r1,
                                      uint32_t& r2, uint32_t& r3) {
    asm volatile("ldmatrix.sync.aligned.m8n8.x4.shared.b16 {%0,%1,%2,%3}, [%4];"
                 : "=r"(r0), "=r"(r1), "=r"(r2), "=r"(r3) : "r"(addr));
}
__device__ __forceinline__ void mma_f16(float* c, const uint32_t* a, const uint32_t* b) {
    asm volatile("mma.sync.aligned.m16n8k16.row.col.f32.f16.f16.f32 "
                 "{%0,%1,%2,%3}, {%4,%5,%6,%7}, {%8,%9}, {%0,%1,%2,%3};"
                 : "+f"(c[0]), "+f"(c[1]), "+f"(c[2]), "+f"(c[3])
                 : "r"(a[0]), "r"(a[1]), "r"(a[2]), "r"(a[3]), "r"(b[0]), "r"(b[1]));
}

// ====== GEMM-A: 8 warps (4x2), BM=128, BN=128, BK=64. For Wo + FF. ======
// EPI: 1 = silu -> fp16 Ch; 2 = + fp16 resid -> fp32 Cf; 3 = + fp16 resid -> fp16 Ch
template <int EPI>
__global__ __launch_bounds__(256, 2) void mma_gemm8(
    int N, int K,
    const __half* __restrict__ A, const __half* __restrict__ B,
    float* __restrict__ Cf, __half* __restrict__ Ch,
    const __half* __restrict__ residh)
{
    constexpr int BN = 128;
    constexpr int NT = BN / 16;
    constexpr int A_BYTES = 128 * 128;
    constexpr int B_BYTES = BN * 128;
    constexpr int STAGE = A_BYTES + B_BYTES;

    extern __shared__ __align__(128) char smem[];
    uint32_t sb = smem_u32(smem);

    const int tid  = threadIdx.x;
    const int lane = tid & 31;
    const int wid  = tid >> 5;
    const int wr   = wid & 3;
    const int wc   = wid >> 2;

    const __half* Ab = A + (size_t)blockIdx.y * 128 * K;
    const __half* Bb = B + (size_t)blockIdx.x * BN * K;

    const int NIT = K >> 6;

    auto load_stage = [&](int s, int kb) {
        uint32_t base = sb + s * STAGE;
        const __half* g = Ab + kb;
        #pragma unroll
        for (int i = tid; i < 1024; i += 256) {
            int r = i >> 3, kc = i & 7;
            cp16(base + r * 128 + ((kc ^ (r & 7)) << 4), g + (size_t)r * K + kc * 8);
        }
        g = Bb + kb;
        uint32_t bdst = base + A_BYTES;
        #pragma unroll
        for (int i = tid; i < BN * 8; i += 256) {
            int r = i >> 3, kc = i & 7;
            cp16(bdst + r * 128 + ((kc ^ (r & 7)) << 4), g + (size_t)r * K + kc * 8);
        }
    };

    auto ld_afrag = [&](uint32_t abase, int ks, uint32_t af[2][4]) {
        #pragma unroll
        for (int mt = 0; mt < 2; mt++) {
            int row = wr * 32 + mt * 16 + (lane & 15);
            int kc  = ks * 2 + (lane >> 4);
            uint32_t off = row * 128 + ((kc ^ (row & 7)) << 4);
            ldsm4(abase + off, af[mt][0], af[mt][1], af[mt][2], af[mt][3]);
        }
    };
    auto ld_bfrag = [&](uint32_t bbase, int ks, uint32_t bf[NT][2]) {
        #pragma unroll
        for (int np = 0; np < NT / 2; np++) {
            int n  = wc * (BN / 2) + np * 16 + ((lane >> 4) << 3) + (lane & 7);
            int kc = ks * 2 + ((lane >> 3) & 1);
            uint32_t off = n * 128 + ((kc ^ (n & 7)) << 4);
            ldsm4(bbase + off, bf[2*np][0], bf[2*np][1], bf[2*np+1][0], bf[2*np+1][1]);
        }
    };

    float acc[2][NT][4];
    #pragma unroll
    for (int mt = 0; mt < 2; mt++)
        #pragma unroll
        for (int nt = 0; nt < NT; nt++)
            #pragma unroll
            for (int j = 0; j < 4; j++) acc[mt][nt][j] = 0.f;

    load_stage(0, 0);
    cp_commit();
    if (NIT > 1) { load_stage(1, 64); cp_commit(); }

    for (int it = 0; it < NIT; it++) {
        if (it + 1 < NIT) cp_wait<1>(); else cp_wait<0>();
        __syncthreads();
        if (it + 2 < NIT) {
            load_stage((it + 2) % 3, (it + 2) << 6);
            cp_commit();
        }

        uint32_t abase = sb + (it % 3) * STAGE;
        uint32_t bbase = abase + A_BYTES;

        uint32_t ah[2][2][4], bbf[NT][2];
        ld_afrag(abase, 0, ah[0]);
        #pragma unroll
        for (int ks = 0; ks < 4; ks++) {
            int cur = ks & 1, nxt = cur ^ 1;
            ld_bfrag(bbase, ks, bbf);
            if (ks < 3) ld_afrag(abase, ks + 1, ah[nxt]);
            #pragma unroll
            for (int mt = 0; mt < 2; mt++)
                #pragma unroll
                for (int nt = 0; nt < NT; nt++) mma_f16(acc[mt][nt], ah[cur][mt], bbf[nt]);
        }
    }

    int rowbase = blockIdx.y * 128 + wr * 32;
    int colbase = blockIdx.x * BN + wc * (BN / 2);
    #pragma unroll
    for (int mt = 0; mt < 2; mt++) {
        #pragma unroll
        for (int nt = 0; nt < NT; nt++) {
            int m = rowbase + mt * 16 + (lane >> 2);
            int n = colbase + nt * 8 + ((lane & 3) << 1);
            float* cc = acc[mt][nt];
            #pragma unroll
            for (int half = 0; half < 2; half++) {
                size_t idx = (size_t)(m + half * 8) * N + n;
                float v0 = cc[half * 2], v1 = cc[half * 2 + 1];
                if (EPI == 1) {
                    v0 = v0 / (1.f + expf(-v0));
                    v1 = v1 / (1.f + expf(-v1));
                    *(__half2*)(Ch + idx) = __floats2half2_rn(v0, v1);
                } else if (EPI == 2) {
                    float2 r2 = __half22float2(*(const __half2*)(residh + idx));
                    float2 o = { v0 + r2.x, v1 + r2.y };
                    *(float2*)(Cf + idx) = o;
                } else {
                    float2 r2 = __half22float2(*(const __half2*)(residh + idx));
                    *(__half2*)(Ch + idx) = __floats2half2_rn(v0 + r2.x, v1 + r2.y);
                }
            }
        }
    }
}

// ====== GEMM-B: 4 warps (2x2), BM=BN=128, warp 64x64 (crossbar-optimal). QKV only. ======
__global__ __launch_bounds__(128, 2) void mma_gemm4(
    int N, int K,
    const __half* __restrict__ A, const __half* __restrict__ B,
    __half* __restrict__ Ch)
{
    constexpr int A_BYTES = 128 * 128;
    constexpr int STAGE = 2 * A_BYTES;   // 32 KB

    extern __shared__ __align__(128) char smem[];
    uint32_t sb = smem_u32(smem);

    const int tid  = threadIdx.x;
    const int lane = tid & 31;
    const int wid  = tid >> 5;
    const int wr   = wid & 1;
    const int wc   = wid >> 1;

    const __half* Ab = A + (size_t)blockIdx.y * 128 * K;
    const __half* Bb = B + (size_t)blockIdx.x * 128 * K;

    const int NIT = K >> 6;

    auto load_stage = [&](int s, int kb) {
        uint32_t base = sb + s * STAGE;
        const __half* g = Ab + kb;
        #pragma unroll
        for (int i = tid; i < 1024; i += 128) {
            int r = i >> 3, kc = i & 7;
            cp16(base + r * 128 + ((kc ^ (r & 7)) << 4), g + (size_t)r * K + kc * 8);
        }
        g = Bb + kb;
        uint32_t bdst = base + A_BYTES;
        #pragma unroll
        for (int i = tid; i < 1024; i += 128) {
            int r = i >> 3, kc = i & 7;
            cp16(bdst + r * 128 + ((kc ^ (r & 7)) << 4), g + (size_t)r * K + kc * 8);
        }
    };

    float acc[4][8][4];
    #pragma unroll
    for (int mt = 0; mt < 4; mt++)
        #pragma unroll
        for (int nt = 0; nt < 8; nt++)
            #pragma unroll
            for (int j = 0; j < 4; j++) acc[mt][nt][j] = 0.f;

    load_stage(0, 0);
    cp_commit();
    if (NIT > 1) { load_stage(1, 64); cp_commit(); }

    for (int it = 0; it < NIT; it++) {
        if (it + 1 < NIT) cp_wait<1>(); else cp_wait<0>();
        __syncthreads();
        if (it + 2 < NIT) {
            load_stage((it + 2) % 3, (it + 2) << 6);
            cp_commit();
        }

        uint32_t abase = sb + (it % 3) * STAGE;
        uint32_t bbase = abase + A_BYTES;

        #pragma unroll
        for (int ks = 0; ks < 4; ks++) {
            uint32_t ah[4][4], bb[8][2];
            #pragma unroll
            for (int mt = 0; mt < 4; mt++) {
                int row = wr * 64 + mt * 16 + (lane & 15);
                int kc  = ks * 2 + (lane >> 4);
                uint32_t off = row * 128 + ((kc ^ (row & 7)) << 4);
                ldsm4(abase + off, ah[mt][0], ah[mt][1], ah[mt][2], ah[mt][3]);
            }
            #pragma unroll
            for (int np = 0; np < 4; np++) {
                int n  = wc * 64 + np * 16 + ((lane >> 4) << 3) + (lane & 7);
                int kc = ks * 2 + ((lane >> 3) & 1);
                uint32_t off = n * 128 + ((kc ^ (n & 7)) << 4);
                ldsm4(bbase + off, bb[2*np][0], bb[2*np][1], bb[2*np+1][0], bb[2*np+1][1]);
            }
            #pragma unroll
            for (int mt = 0; mt < 4; mt++)
                #pragma unroll
                for (int nt = 0; nt < 8; nt++) mma_f16(acc[mt][nt], ah[mt], bb[nt]);
        }
    }

    int rowbase = blockIdx.y * 128 + wr * 64;
    int colbase = blockIdx.x * 128 + wc * 64;
    #pragma unroll
    for (int mt = 0; mt < 4; mt++) {
        #pragma unroll
        for (int nt = 0; nt < 8; nt++) {
            int m = rowbase + mt * 16 + (lane >> 2);
            int n = colbase + nt * 8 + ((lane & 3) << 1);
            float* cc = acc[mt][nt];
            #pragma unroll
            for (int half = 0; half < 2; half++) {
                size_t idx = (size_t)(m + half * 8) * N + n;
                *(__half2*)(Ch + idx) = __floats2half2_rn(cc[half * 2], cc[half * 2 + 1]);
            }
        }
    }
}

// ================= single prep kernel: all weight transposes to fp16 =================
__global__ void prep_kernel(const float* __restrict__ Wq, const float* __restrict__ Wk,
                            const float* __restrict__ Wv, const float* __restrict__ Wg,
                            const float* __restrict__ Wo, const float* __restrict__ ff1,
                            const float* __restrict__ ff2,
                            __half* __restrict__ wqkvT, __half* __restrict__ woT,
                            __half* __restrict__ f1T, __half* __restrict__ f2T) {
    int id = blockIdx.x;
    int tx = threadIdx.x, ty = threadIdx.y;  // 32 x 8
    __shared__ float t[32][33];

    const float* W; __half* T; int K, N, tt, rowoff = 0;
    if (id < 64)        { W = Wq;  T = wqkvT; K = DD;  N = AD;  tt = id;        rowoff = 0; }
    else if (id < 128)  { W = Wk;  T = wqkvT; K = DD;  N = AD;  tt = id - 64;   rowoff = 64; }
    else if (id < 192)  { W = Wv;  T = wqkvT; K = DD;  N = AD;  tt = id - 128;  rowoff = 128; }
    else if (id < 256) {
        int row = id;  // 192..255: row 192 = Wg, rest zero
        int lt = ty * 32 + tx;
        for (int c = lt; c < DD; c += 256)
            wqkvT[(size_t)row * DD + c] = (row == 192) ? __float2half(Wg[c]) : __half(0.f);
        return;
    }
    else if (id < 2304) { W = ff1; T = f1T;   K = DD;  N = FFD; tt = id - 256; }
    else if (id < 4352) { W = ff2; T = f2T;   K = FFD; N = DD;  tt = id - 2304; }
    else                { W = Wo;  T = woT;   K = AD;  N = DD;  tt = id - 4352; }

    int ntiles = N / 32;
    int nb = (tt % ntiles) * 32, kb = (tt / ntiles) * 32;
    #pragma unroll
    for (int i = 0; i < 32; i += 8) t[ty + i][tx] = W[(size_t)(kb + ty + i) * N + nb + tx];
    __syncthreads();
    #pragma unroll
    for (int i = 0; i < 32; i += 8)
        T[(size_t)(rowoff + nb + ty + i) * K + kb + tx] = __float2half(t[tx][ty + i]);
}

// ---------------- warp-per-token rms + flags reset ----------------
__global__ __launch_bounds__(256) void rms_kernel(const float* __restrict__ x,
                                                  float* __restrict__ rinv,
                                                  int* __restrict__ flags) {
    if (blockIdx.x == 0 && threadIdx.x < 256) {
        flags[threadIdx.x] = 0;
        flags[threadIdx.x + 256] = 0;
    }
    int tok = blockIdx.x * 8 + (threadIdx.x >> 5);
    int lane = threadIdx.x & 31;
    const float4* xr = (const float4*)(x + (size_t)tok * DD);
    float ss = 0.f;
    #pragma unroll
    for (int i = 0; i < 8; i++) {
        float4 v = xr[lane + i * 32];
        ss += v.x*v.x + v.y*v.y + v.z*v.z + v.w*v.w;
    }
    #pragma unroll
    for (int o = 16; o > 0; o >>= 1) ss += __shfl_xor_sync(~0u, ss, o);
    if (lane == 0) rinv[tok] = rsqrtf(ss * (1.0f / DD) + EPSR);
}

// ---------------- warp-per-token rmsnorm2: fp16 in, fp16 out ----------------
__global__ __launch_bounds__(256) void rmsnorm2_kernel(const __half* __restrict__ x,
                                                       const float* __restrict__ w,
                                                       __half* __restrict__ outh) {
    int tok = blockIdx.x * 8 + (threadIdx.x >> 5);
    int lane = threadIdx.x & 31;
    const uint4* xr = (const uint4*)(x + (size_t)tok * DD);   // 8 halves per uint4
    float f[4][8];
    float ss = 0.f;
    #pragma unroll
    for (int i = 0; i < 4; i++) {
        uint4 v = xr[lane + i * 32];
        const __half2* h = (const __half2*)&v;
        #pragma unroll
        for (int j = 0; j < 4; j++) {
            float2 p = __half22float2(h[j]);
            f[i][2*j] = p.x; f[i][2*j+1] = p.y;
            ss += p.x*p.x + p.y*p.y;
        }
    }
    #pragma unroll
    for (int o = 16; o > 0; o >>= 1) ss += __shfl_xor_sync(~0u, ss, o);
    float r = rsqrtf(ss * (1.0f / DD) + EPSR);
    #pragma unroll
    for (int i = 0; i < 4; i++) {
        int base8 = (lane + i * 32) * 8;
        size_t ob = (size_t)tok * DD + base8;
        #pragma unroll
        for (int j = 0; j < 4; j++) {
            float2 wv = *(const float2*)(w + base8 + 2*j);
            *(__half2*)(outh + ob + 2*j) =
                __floats2half2_rn(f[i][2*j] * r * wv.x, f[i][2*j+1] * r * wv.y);
        }
    }
}

// ---------------- fused SSM scan: decoupled lookback; fp16 x_ssm output only ----------------
__global__ __launch_bounds__(128) void scan_fused(
    const float* __restrict__ x, const float* __restrict__ rinv,
    const float* __restrict__ n1w, const float* __restrict__ b_w,
    const float* __restrict__ a_raw, const float* __restrict__ c_w,
    float* __restrict__ agg, float* __restrict__ incl, int* __restrict__ flags,
    __half* __restrict__ xh)
{
    int blk = blockIdx.x;            // b*NCHUNK + c
    int half = blockIdx.y;
    int c = blk & (NCHUNK - 1);
    int t = threadIdx.x;
    int d4 = half * 128 + t;
    int fidx = blk * 2 + half;
    int tok0 = blk * CHUNK;

    float4 w1 = ((const float4*)n1w)[d4];
    float4 w2 = ((const float4*)b_w)[d4];
    float4 wc = { w1.x*w2.x, w1.y*w2.y, w1.z*w2.z, w1.w*w2.w };
    float4 cw = ((const float4*)c_w)[d4];
    float4 ar = ((const float4*)a_raw)[d4];
    float a0 = sigmoidf_(ar.x), a1 = sigmoidf_(ar.y), a2 = sigmoidf_(ar.z), a3 = sigmoidf_(ar.w);
    float aC0 = a0, aC1 = a1, aC2 = a2, aC3 = a3;
    #pragma unroll
    for (int i = 0; i < 6; i++) { aC0 *= aC0; aC1 *= aC1; aC2 *= aC2; aC3 *= aC3; }

    const float4* xp = (const float4*)(x + (size_t)tok0 * DD) + d4;
    const float* rp = rinv + tok0;

    float h0 = 0.f, h1 = 0.f, h2 = 0.f, h3 = 0.f;
    #pragma unroll 4
    for (int i = 0; i < CHUNK; i++) {
        float r = rp[i];
        float4 xv = xp[(size_t)i * 256];
        h0 = fmaf(a0, h0, xv.x * r * wc.x);
        h1 = fmaf(a1, h1, xv.y * r * wc.y);
        h2 = fmaf(a2, h2, xv.z * r * wc.z);
        h3 = fmaf(a3, h3, xv.w * r * wc.w);
    }

    float e0 = 0.f, e1 = 0.f, e2 = 0.f, e3 = 0.f;
    __shared__ int sflag;
    if (c == 0) {
        float4 iv = { h0, h1, h2, h3 };
        ((float4*)(incl + (size_t)blk * DD))[d4] = iv;
        __threadfence();
        __syncthreads();
        if (t == 0) atomicExch(&flags[fidx], 2);
    } else {
        float4 av = { h0, h1, h2, h3 };
        ((float4*)(agg + (size_t)blk * DD))[d4] = av;
        __threadfence();
        __syncthreads();
        if (t == 0) atomicExch(&flags[fidx], 1);
        float f0 = 1.f, f1 = 1.f, f2 = 1.f, f3 = 1.f;
        int j = blk - 1;
        while (true) {
            if (t == 0) {
                int fl;
                do { fl = atomicOr(&flags[j * 2 + half], 0); } while (fl == 0);
                sflag = fl;
            }
            __syncthreads();
            int fl = sflag;
            __threadfence();
            if (fl == 2) {
                float4 pv = ((const float4*)(incl + (size_t)j * DD))[d4];
                e0 = fmaf(f0, pv.x, e0); e1 = fmaf(f1, pv.y, e1);
                e2 = fmaf(f2, pv.z, e2); e3 = fmaf(f3, pv.w, e3);
                break;
            } else {
                float4 pv = ((const float4*)(agg + (size_t)j * DD))[d4];
                e0 = fmaf(f0, pv.x, e0); e1 = fmaf(f1, pv.y, e1);
                e2 = fmaf(f2, pv.z, e2); e3 = fmaf(f3, pv.w, e3);
                f0 *= aC0; f1 *= aC1; f2 *= aC2; f3 *= aC3;
                j--;
            }
            __syncthreads();
        }
        float4 iv = { fmaf(aC0, e0, h0), fmaf(aC1, e1, h1),
                      fmaf(aC2, e2, h2), fmaf(aC3, e3, h3) };
        ((float4*)(incl + (size_t)blk * DD))[d4] = iv;
        __threadfence();
        __syncthreads();
        if (t == 0) atomicExch(&flags[fidx], 2);
    }

    h0 = e0; h1 = e1; h2 = e2; h3 = e3;
    #pragma unroll 4
    for (int i = 0; i < CHUNK; i++) {
        float r = rp[i];
        float4 xv = xp[(size_t)i * 256];
        h0 = fmaf(a0, h0, xv.x * r * wc.x);
        h1 = fmaf(a1, h1, xv.y * r * wc.y);
        h2 = fmaf(a2, h2, xv.z * r * wc.z);
        h3 = fmaf(a3, h3, xv.w * r * wc.w);
        size_t ho = ((size_t)tok0 + i) * DD + (size_t)d4 * 4;
        *(__half2*)(xh + ho)     = __floats2half2_rn(xv.x + h0 * cw.x, xv.y + h1 * cw.y);
        *(__half2*)(xh + ho + 2) = __floats2half2_rn(xv.z + h2 * cw.z, xv.w + h3 * cw.w);
    }
}

// ---------------- warp-per-token sliding-window attention: 64 tokens/block ----------------
#define KV_STRIDE 66
#define ATTN_KS   0
#define ATTN_VS   16768
#define ATTN_QS   33536
#define ATTN_PS   35584
#define ATTN_SMEM 37632

__global__ __launch_bounds__(256) void attn_kernel(const __half* __restrict__ QKV,
                                                   const float* __restrict__ bias,
                                                   __half* __restrict__ ga) {
    extern __shared__ __align__(16) char smem[];
    __half* Ks = (__half*)(smem + ATTN_KS);
    __half* Vs = (__half*)(smem + ATTN_VS);
    float*  qs = (float*)(smem + ATTN_QS);
    float*  ps = (float*)(smem + ATTN_PS);

    int tok0 = blockIdx.x * 64;
    int b = tok0 / LL, l0 = tok0 % LL;
    int tid = threadIdx.x, lane = tid & 31, warp = tid >> 5;
    float gb = bias[0];

    for (int idx = tid; idx < 127 * 32; idx += 256) {
        int s = idx >> 5, dp = idx & 31;
        int r = l0 - 63 + s;
        __half2 kk = __floats2half2_rn(0.f, 0.f), vv = kk;
        if (r >= 0) {
            const __half* row = QKV + ((size_t)b * LL + r) * QKVN;
            kk = *(const __half2*)(row + 64 + dp * 2);
            vv = *(const __half2*)(row + 128 + dp * 2);
        }
        *(__half2*)(Ks + s * KV_STRIDE + dp * 2) = kk;
        *(__half2*)(Vs + s * KV_STRIDE + dp * 2) = vv;
    }
    __syncthreads();

    float* qw = qs + warp * 64;
    float* pw = ps + warp * 64;

    for (int it = 0; it < 8; it++) {
        int i = it * 8 + warp;
        int tkn = tok0 + i;
        const __half* qrow = QKV + (size_t)tkn * QKVN;
        qw[lane] = __half2float(qrow[lane]);
        qw[lane + 32] = __half2float(qrow[lane + 32]);
        float sg = 0.f;
        if (lane == 0) sg = sigmoidf_(__half2float(qrow[192]) + gb);
        sg = __shfl_sync(~0u, sg, 0);
        __syncwarp();

        int w0 = lane * 2;
        float s0 = 0.f, s1 = 0.f;
        const __half* k0 = Ks + (i + w0) * KV_STRIDE;
        const __half* k1 = k0 + KV_STRIDE;
        #pragma unroll 8
        for (int d = 0; d < AD; d += 2) {
            float q0 = qw[d], q1 = qw[d + 1];
            float2 ka = __half22float2(*(const __half2*)(k0 + d));
            float2 kb = __half22float2(*(const __half2*)(k1 + d));
            s0 = fmaf(q0, ka.x, fmaf(q1, ka.y, s0));
            s1 = fmaf(q0, kb.x, fmaf(q1, kb.y, s1));
        }
        bool v0 = (l0 + i - 63 + w0) >= 0;
        bool v1 = (l0 + i - 62 + w0) >= 0;
        s0 = v0 ? s0 * 0.125f : -INFINITY;
        s1 = v1 ? s1 * 0.125f : -INFINITY;
        float m = fmaxf(s0, s1);
        #pragma unroll
        for (int o = 16; o > 0; o >>= 1) m = fmaxf(m, __shfl_xor_sync(~0u, m, o));
        float e0 = v0 ? expf(s0 - m) : 0.f;
        float e1 = v1 ? expf(s1 - m) : 0.f;
        float sum = e0 + e1;
        #pragma unroll
        for (int o = 16; o > 0; o >>= 1) sum += __shfl_xor_sync(~0u, sum, o);
        float inv = sg / sum;
        *(float2*)(pw + w0) = make_float2(e0, e1);
        __syncwarp();

        float a0 = 0.f, a1 = 0.f;
        #pragma unroll 8
        for (int w = 0; w < WW; w++) {
            float p = pw[w];
            float2 vv = __half22float2(*(const __half2*)(Vs + (i + w) * KV_STRIDE + w0));
            a0 = fmaf(p, vv.x, a0);
            a1 = fmaf(p, vv.y, a1);
        }
        *(__half2*)(ga + (size_t)tkn * AD + w0) = __floats2half2_rn(a0 * inv, a1 * inv);
        __syncwarp();
    }
}

// ---------------- launcher ----------------
extern "C" void kernel_launch(void* const* d_in, const int* in_sizes, int n_in,
                              void* d_out, int out_size) {
    (void)in_sizes; (void)n_in; (void)out_size;
    const float* x     = (const float*)d_in[0];
    const float* n1w   = (const float*)d_in[1];
    const float* n2w   = (const float*)d_in[2];
    const float* a_raw = (const float*)d_in[3];
    const float* b_w   = (const float*)d_in[4];
    const float* c_w   = (const float*)d_in[5];
    const float* Wq    = (const float*)d_in[6];
    const float* Wk    = (const float*)d_in[7];
    const float* Wv    = (const float*)d_in[8];
    const float* Wo    = (const float*)d_in[9];
    const float* Wg    = (const float*)d_in[10];
    const float* gbias = (const float*)d_in[11];
    const float* ff1   = (const float*)d_in[12];
    const float* ff2   = (const float*)d_in[13];
    float* out = (float*)d_out;

    float *p_rinv, *p_agg, *p_incl;
    int *p_flags;
    __half *p_xh, *p_n2h, *p_tmp, *p_ga, *p_qkvh, *p_wqkv, *p_woT, *p_f1T, *p_f2T;
    cudaGetSymbolAddress((void**)&p_rinv, g_rinv);
    cudaGetSymbolAddress((void**)&p_agg, g_agg);
    cudaGetSymbolAddress((void**)&p_incl, g_incl);
    cudaGetSymbolAddress((void**)&p_flags, g_flags);
    cudaGetSymbolAddress((void**)&p_xh, g_xh);
    cudaGetSymbolAddress((void**)&p_n2h, g_n2h);
    cudaGetSymbolAddress((void**)&p_tmp, g_tmp);
    cudaGetSymbolAddress((void**)&p_ga, g_ga);
    cudaGetSymbolAddress((void**)&p_qkvh, g_qkvh);
    cudaGetSymbolAddress((void**)&p_wqkv, g_wqkvT);
    cudaGetSymbolAddress((void**)&p_woT, g_woT);
    cudaGetSymbolAddress((void**)&p_f1T, g_f1T);
    cudaGetSymbolAddress((void**)&p_f2T, g_f2T);

    const int SMEM_8 = 3 * (16384 + 16384);  // 98304
    const int SMEM_4 = 3 * (16384 + 16384);  // 98304
    cudaFuncSetAttribute(mma_gemm8<1>, cudaFuncAttributeMaxDynamicSharedMemorySize, SMEM_8);
    cudaFuncSetAttribute(mma_gemm8<2>, cudaFuncAttributeMaxDynamicSharedMemorySize, SMEM_8);
    cudaFuncSetAttribute(mma_gemm8<3>, cudaFuncAttributeMaxDynamicSharedMemorySize, SMEM_8);
    cudaFuncSetAttribute(mma_gemm4, cudaFuncAttributeMaxDynamicSharedMemorySize, SMEM_4);
    cudaFuncSetAttribute(attn_kernel, cudaFuncAttributeMaxDynamicSharedMemorySize, ATTN_SMEM);

    // 0) weight prep
    prep_kernel<<<4416, dim3(32, 8)>>>(Wq, Wk, Wv, Wg, Wo, ff1, ff2,
                                       p_wqkv, p_woT, p_f1T, p_f2T);
    // 1) per-token rms of x + flag reset
    rms_kernel<<<MROWS / 8, 256>>>(x, p_rinv, p_flags);
    // 2) fused decoupled-lookback SSM scan -> fp16 x_ssm
    scan_fused<<<dim3(BB * NCHUNK, 2), 128>>>(x, p_rinv, n1w, b_w, a_raw, c_w,
                                              p_agg, p_incl, p_flags, p_xh);
    // 3) fused QKV+gate projection -> fp16 (4-warp crossbar-optimal)
    {
        dim3 grid(QKVN / 128, MROWS / 128);
        mma_gemm4<<<grid, 128, SMEM_4>>>(QKVN, DD, p_xh, p_wqkv, p_qkvh);
    }
    // 4) attention + gate -> ga fp16 (64 tokens/block)
    attn_kernel<<<MROWS / 64, 256, ATTN_SMEM>>>(p_qkvh, gbias, p_ga);
    // 5) xh += ga @ WoT (fp16 residual, in-place)
    {
        dim3 grid(DD / 128, MROWS / 128);
        mma_gemm8<3><<<grid, 256, SMEM_8>>>(DD, AD, p_ga, p_woT, nullptr, p_xh, p_xh);
    }
    // 6) n2 = rmsnorm(xh)*n2w -> fp16
    rmsnorm2_kernel<<<MROWS / 8, 256>>>(p_xh, n2w, p_n2h);
    // 7) tmp = silu(n2 @ ff_w1) -> fp16
    {
        dim3 grid(FFD / 128, MROWS / 128);
        mma_gemm8<1><<<grid, 256, SMEM_8>>>(FFD, DD, p_n2h, p_f1T, nullptr, p_tmp, nullptr);
    }
    // 8) out = xh + tmp @ ff_w2 (fp32 output)
    {
        dim3 grid(DD / 128, MROWS / 128);
        mma_gemm8<2><<<grid, 256, SMEM_8>>>(DD, FFD, p_tmp, p_f2T, out, nullptr, p_xh);
    }
}

// round 17
// speedup vs baseline: 1.0995x; 1.0236x over previous
#include <cuda_runtime.h>
#include <cuda_fp16.h>
#include <cstdint>
#include <math.h>

// ---------------- problem constants ----------------
#define BB     4
#define LL     4096
#define DD     1024
#define AD     64
#define WW     64
#define FFD    2048
#define MROWS  (BB*LL)
#define CHUNK  64
#define NCHUNK (LL/CHUNK)
#define EPSR   1e-6f
#define QKVN   256         // q|k|v|gate padded width

// ---------------- scratch ----------------
__device__ float  g_rinv[MROWS];                 // rms of x, later reused for rms of xh
__device__ __half g_xh[(size_t)MROWS*DD];        // fp16 x_ssm (residual stream)
__device__ __half g_tmp[(size_t)MROWS*FFD];
__device__ __half g_ga[(size_t)MROWS*AD];
__device__ float  g_agg[(size_t)BB*NCHUNK*DD];
__device__ float  g_incl[(size_t)BB*NCHUNK*DD];
__device__ int    g_flags[BB*NCHUNK*2];
__device__ __half g_qkvh[(size_t)MROWS*QKVN];
__device__ __half g_wqkvT[(size_t)QKVN*DD];
__device__ __half g_woT[(size_t)DD*AD];
__device__ __half g_f1T[(size_t)FFD*DD];         // includes n2w fold
__device__ __half g_f2T[(size_t)DD*FFD];

__device__ __forceinline__ float sigmoidf_(float x) { return 1.0f / (1.0f + expf(-x)); }

__device__ __forceinline__ uint32_t smem_u32(const void* p) {
    uint32_t a;
    asm("{ .reg .u64 t; cvta.to.shared.u64 t, %1; cvt.u32.u64 %0, t; }" : "=r"(a) : "l"(p));
    return a;
}
__device__ __forceinline__ void cp16(uint32_t dst, const void* src) {
    asm volatile("cp.async.cg.shared.global [%0], [%1], 16;" :: "r"(dst), "l"(src));
}
__device__ __forceinline__ void cp_commit() { asm volatile("cp.async.commit_group;"); }
template <int N> __device__ __forceinline__ void cp_wait() {
    asm volatile("cp.async.wait_group %0;" :: "n"(N) : "memory");
}
__device__ __forceinline__ void ldsm4(uint32_t addr, uint32_t& r0, uint32_t& r1,
                                      uint32_t& r2, uint32_t& r3) {
    asm volatile("ldmatrix.sync.aligned.m8n8.x4.shared.b16 {%0,%1,%2,%3}, [%4];"
                 : "=r"(r0), "=r"(r1), "=r"(r2), "=r"(r3) : "r"(addr));
}
__device__ __forceinline__ void mma_f16(float* c, const uint32_t* a, const uint32_t* b) {
    asm volatile("mma.sync.aligned.m16n8k16.row.col.f32.f16.f16.f32 "
                 "{%0,%1,%2,%3}, {%4,%5,%6,%7}, {%8,%9}, {%0,%1,%2,%3};"
                 : "+f"(c[0]), "+f"(c[1]), "+f"(c[2]), "+f"(c[3])
                 : "r"(a[0]), "r"(a[1]), "r"(a[2]), "r"(a[3]), "r"(b[0]), "r"(b[1]));
}

// ====== GEMM-A: 8 warps (4x2), BM=128, BN=128, BK=64. For Wo + FF. ======
// EPI: 1 = rowscale + silu -> fp16 Ch; 2 = + fp16 resid -> fp32 Cf; 3 = + fp16 resid -> fp16 Ch
template <int EPI>
__global__ __launch_bounds__(256, 2) void mma_gemm8(
    int N, int K,
    const __half* __restrict__ A, const __half* __restrict__ B,
    float* __restrict__ Cf, __half* __restrict__ Ch,
    const __half* __restrict__ residh, const float* __restrict__ rowscale)
{
    constexpr int BN = 128;
    constexpr int NT = BN / 16;
    constexpr int A_BYTES = 128 * 128;
    constexpr int B_BYTES = BN * 128;
    constexpr int STAGE = A_BYTES + B_BYTES;

    extern __shared__ __align__(128) char smem[];
    uint32_t sb = smem_u32(smem);

    const int tid  = threadIdx.x;
    const int lane = tid & 31;
    const int wid  = tid >> 5;
    const int wr   = wid & 3;
    const int wc   = wid >> 2;

    const __half* Ab = A + (size_t)blockIdx.y * 128 * K;
    const __half* Bb = B + (size_t)blockIdx.x * BN * K;

    const int NIT = K >> 6;

    auto load_stage = [&](int s, int kb) {
        uint32_t base = sb + s * STAGE;
        const __half* g = Ab + kb;
        #pragma unroll
        for (int i = tid; i < 1024; i += 256) {
            int r = i >> 3, kc = i & 7;
            cp16(base + r * 128 + ((kc ^ (r & 7)) << 4), g + (size_t)r * K + kc * 8);
        }
        g = Bb + kb;
        uint32_t bdst = base + A_BYTES;
        #pragma unroll
        for (int i = tid; i < BN * 8; i += 256) {
            int r = i >> 3, kc = i & 7;
            cp16(bdst + r * 128 + ((kc ^ (r & 7)) << 4), g + (size_t)r * K + kc * 8);
        }
    };

    auto ld_afrag = [&](uint32_t abase, int ks, uint32_t af[2][4]) {
        #pragma unroll
        for (int mt = 0; mt < 2; mt++) {
            int row = wr * 32 + mt * 16 + (lane & 15);
            int kc  = ks * 2 + (lane >> 4);
            uint32_t off = row * 128 + ((kc ^ (row & 7)) << 4);
            ldsm4(abase + off, af[mt][0], af[mt][1], af[mt][2], af[mt][3]);
        }
    };
    auto ld_bfrag = [&](uint32_t bbase, int ks, uint32_t bf[NT][2]) {
        #pragma unroll
        for (int np = 0; np < NT / 2; np++) {
            int n  = wc * (BN / 2) + np * 16 + ((lane >> 4) << 3) + (lane & 7);
            int kc = ks * 2 + ((lane >> 3) & 1);
            uint32_t off = n * 128 + ((kc ^ (n & 7)) << 4);
            ldsm4(bbase + off, bf[2*np][0], bf[2*np][1], bf[2*np+1][0], bf[2*np+1][1]);
        }
    };

    float acc[2][NT][4];
    #pragma unroll
    for (int mt = 0; mt < 2; mt++)
        #pragma unroll
        for (int nt = 0; nt < NT; nt++)
            #pragma unroll
            for (int j = 0; j < 4; j++) acc[mt][nt][j] = 0.f;

    load_stage(0, 0);
    cp_commit();
    if (NIT > 1) { load_stage(1, 64); cp_commit(); }

    for (int it = 0; it < NIT; it++) {
        if (it + 1 < NIT) cp_wait<1>(); else cp_wait<0>();
        __syncthreads();
        if (it + 2 < NIT) {
            load_stage((it + 2) % 3, (it + 2) << 6);
            cp_commit();
        }

        uint32_t abase = sb + (it % 3) * STAGE;
        uint32_t bbase = abase + A_BYTES;

        uint32_t ah[2][2][4], bbf[NT][2];
        ld_afrag(abase, 0, ah[0]);
        #pragma unroll
        for (int ks = 0; ks < 4; ks++) {
            int cur = ks & 1, nxt = cur ^ 1;
            ld_bfrag(bbase, ks, bbf);
            if (ks < 3) ld_afrag(abase, ks + 1, ah[nxt]);
            #pragma unroll
            for (int mt = 0; mt < 2; mt++)
                #pragma unroll
                for (int nt = 0; nt < NT; nt++) mma_f16(acc[mt][nt], ah[cur][mt], bbf[nt]);
        }
    }

    int rowbase = blockIdx.y * 128 + wr * 32;
    int colbase = blockIdx.x * BN + wc * (BN / 2);
    #pragma unroll
    for (int mt = 0; mt < 2; mt++) {
        int m0 = rowbase + mt * 16 + (lane >> 2);
        float rs0 = 0.f, rs1 = 0.f;
        if (EPI == 1) { rs0 = rowscale[m0]; rs1 = rowscale[m0 + 8]; }
        #pragma unroll
        for (int nt = 0; nt < NT; nt++) {
            int n = colbase + nt * 8 + ((lane & 3) << 1);
            float* cc = acc[mt][nt];
            #pragma unroll
            for (int half = 0; half < 2; half++) {
                size_t idx = (size_t)(m0 + half * 8) * N + n;
                float v0 = cc[half * 2], v1 = cc[half * 2 + 1];
                if (EPI == 1) {
                    float rs = half ? rs1 : rs0;
                    v0 *= rs; v1 *= rs;
                    v0 = v0 / (1.f + expf(-v0));
                    v1 = v1 / (1.f + expf(-v1));
                    *(__half2*)(Ch + idx) = __floats2half2_rn(v0, v1);
                } else if (EPI == 2) {
                    float2 r2 = __half22float2(*(const __half2*)(residh + idx));
                    float2 o = { v0 + r2.x, v1 + r2.y };
                    *(float2*)(Cf + idx) = o;
                } else {
                    float2 r2 = __half22float2(*(const __half2*)(residh + idx));
                    *(__half2*)(Ch + idx) = __floats2half2_rn(v0 + r2.x, v1 + r2.y);
                }
            }
        }
    }
}

// ====== GEMM-B: 4 warps (2x2), BM=BN=128, warp 64x64 (crossbar-optimal). QKV only. ======
__global__ __launch_bounds__(128, 2) void mma_gemm4(
    int N, int K,
    const __half* __restrict__ A, const __half* __restrict__ B,
    __half* __restrict__ Ch)
{
    constexpr int A_BYTES = 128 * 128;
    constexpr int STAGE = 2 * A_BYTES;   // 32 KB

    extern __shared__ __align__(128) char smem[];
    uint32_t sb = smem_u32(smem);

    const int tid  = threadIdx.x;
    const int lane = tid & 31;
    const int wid  = tid >> 5;
    const int wr   = wid & 1;
    const int wc   = wid >> 1;

    const __half* Ab = A + (size_t)blockIdx.y * 128 * K;
    const __half* Bb = B + (size_t)blockIdx.x * 128 * K;

    const int NIT = K >> 6;

    auto load_stage = [&](int s, int kb) {
        uint32_t base = sb + s * STAGE;
        const __half* g = Ab + kb;
        #pragma unroll
        for (int i = tid; i < 1024; i += 128) {
            int r = i >> 3, kc = i & 7;
            cp16(base + r * 128 + ((kc ^ (r & 7)) << 4), g + (size_t)r * K + kc * 8);
        }
        g = Bb + kb;
        uint32_t bdst = base + A_BYTES;
        #pragma unroll
        for (int i = tid; i < 1024; i += 128) {
            int r = i >> 3, kc = i & 7;
            cp16(bdst + r * 128 + ((kc ^ (r & 7)) << 4), g + (size_t)r * K + kc * 8);
        }
    };

    float acc[4][8][4];
    #pragma unroll
    for (int mt = 0; mt < 4; mt++)
        #pragma unroll
        for (int nt = 0; nt < 8; nt++)
            #pragma unroll
            for (int j = 0; j < 4; j++) acc[mt][nt][j] = 0.f;

    load_stage(0, 0);
    cp_commit();
    if (NIT > 1) { load_stage(1, 64); cp_commit(); }

    for (int it = 0; it < NIT; it++) {
        if (it + 1 < NIT) cp_wait<1>(); else cp_wait<0>();
        __syncthreads();
        if (it + 2 < NIT) {
            load_stage((it + 2) % 3, (it + 2) << 6);
            cp_commit();
        }

        uint32_t abase = sb + (it % 3) * STAGE;
        uint32_t bbase = abase + A_BYTES;

        #pragma unroll
        for (int ks = 0; ks < 4; ks++) {
            uint32_t ah[4][4], bb[8][2];
            #pragma unroll
            for (int mt = 0; mt < 4; mt++) {
                int row = wr * 64 + mt * 16 + (lane & 15);
                int kc  = ks * 2 + (lane >> 4);
                uint32_t off = row * 128 + ((kc ^ (row & 7)) << 4);
                ldsm4(abase + off, ah[mt][0], ah[mt][1], ah[mt][2], ah[mt][3]);
            }
            #pragma unroll
            for (int np = 0; np < 4; np++) {
                int n  = wc * 64 + np * 16 + ((lane >> 4) << 3) + (lane & 7);
                int kc = ks * 2 + ((lane >> 3) & 1);
                uint32_t off = n * 128 + ((kc ^ (n & 7)) << 4);
                ldsm4(bbase + off, bb[2*np][0], bb[2*np][1], bb[2*np+1][0], bb[2*np+1][1]);
            }
            #pragma unroll
            for (int mt = 0; mt < 4; mt++)
                #pragma unroll
                for (int nt = 0; nt < 8; nt++) mma_f16(acc[mt][nt], ah[mt], bb[nt]);
        }
    }

    int rowbase = blockIdx.y * 128 + wr * 64;
    int colbase = blockIdx.x * 128 + wc * 64;
    #pragma unroll
    for (int mt = 0; mt < 4; mt++) {
        #pragma unroll
        for (int nt = 0; nt < 8; nt++) {
            int m = rowbase + mt * 16 + (lane >> 2);
            int n = colbase + nt * 8 + ((lane & 3) << 1);
            float* cc = acc[mt][nt];
            #pragma unroll
            for (int half = 0; half < 2; half++) {
                size_t idx = (size_t)(m + half * 8) * N + n;
                *(__half2*)(Ch + idx) = __floats2half2_rn(cc[half * 2], cc[half * 2 + 1]);
            }
        }
    }
}

// ========= prep kernel: weight transposes (f1T folds n2w) + rms of x + flag reset =========
// ids [0,4416): weight tiles.  ids [4416, 4416+2048): rms over x (8 tokens each).
__global__ void prep_kernel(const float* __restrict__ Wq, const float* __restrict__ Wk,
                            const float* __restrict__ Wv, const float* __restrict__ Wg,
                            const float* __restrict__ Wo, const float* __restrict__ ff1,
                            const float* __restrict__ ff2, const float* __restrict__ n2w,
                            const float* __restrict__ x,
                            __half* __restrict__ wqkvT, __half* __restrict__ woT,
                            __half* __restrict__ f1T, __half* __restrict__ f2T,
                            float* __restrict__ rinv, int* __restrict__ flags) {
    int id = blockIdx.x;
    int tx = threadIdx.x, ty = threadIdx.y;  // 32 x 8

    if (id >= 4416) {
        int bid = id - 4416;                 // 0..2047
        int lt = ty * 32 + tx;
        if (bid == 0) { flags[lt] = 0; flags[lt + 256] = 0; }
        int tok = bid * 8 + (lt >> 5);
        int lane = lt & 31;
        const float4* xr = (const float4*)(x + (size_t)tok * DD);
        float ss = 0.f;
        #pragma unroll
        for (int i = 0; i < 8; i++) {
            float4 v = xr[lane + i * 32];
            ss += v.x*v.x + v.y*v.y + v.z*v.z + v.w*v.w;
        }
        #pragma unroll
        for (int o = 16; o > 0; o >>= 1) ss += __shfl_xor_sync(~0u, ss, o);
        if (lane == 0) rinv[tok] = rsqrtf(ss * (1.0f / DD) + EPSR);
        return;
    }

    __shared__ float t[32][33];
    const float* W; __half* T; int K, N, tt, rowoff = 0;
    bool fold = false;
    if (id < 64)        { W = Wq;  T = wqkvT; K = DD;  N = AD;  tt = id;        rowoff = 0; }
    else if (id < 128)  { W = Wk;  T = wqkvT; K = DD;  N = AD;  tt = id - 64;   rowoff = 64; }
    else if (id < 192)  { W = Wv;  T = wqkvT; K = DD;  N = AD;  tt = id - 128;  rowoff = 128; }
    else if (id < 256) {
        int row = id;  // 192..255: row 192 = Wg, rest zero
        int lt = ty * 32 + tx;
        for (int c = lt; c < DD; c += 256)
            wqkvT[(size_t)row * DD + c] = (row == 192) ? __float2half(Wg[c]) : __half(0.f);
        return;
    }
    else if (id < 2304) { W = ff1; T = f1T;   K = DD;  N = FFD; tt = id - 256; fold = true; }
    else if (id < 4352) { W = ff2; T = f2T;   K = FFD; N = DD;  tt = id - 2304; }
    else                { W = Wo;  T = woT;   K = AD;  N = DD;  tt = id - 4352; }

    int ntiles = N / 32;
    int nb = (tt % ntiles) * 32, kb = (tt / ntiles) * 32;
    #pragma unroll
    for (int i = 0; i < 32; i += 8) t[ty + i][tx] = W[(size_t)(kb + ty + i) * N + nb + tx];
    __syncthreads();
    float wk = fold ? n2w[kb + tx] : 1.0f;
    #pragma unroll
    for (int i = 0; i < 32; i += 8)
        T[(size_t)(rowoff + nb + ty + i) * K + kb + tx] = __float2half(t[tx][ty + i] * wk);
}

// ---------------- warp-per-token rms over fp16 xh -> rinv (reused buffer) ----------------
__global__ __launch_bounds__(256) void rms2h_kernel(const __half* __restrict__ x,
                                                    float* __restrict__ rinv) {
    int tok = blockIdx.x * 8 + (threadIdx.x >> 5);
    int lane = threadIdx.x & 31;
    const uint4* xr = (const uint4*)(x + (size_t)tok * DD);
    float ss = 0.f;
    #pragma unroll
    for (int i = 0; i < 4; i++) {
        uint4 v = xr[lane + i * 32];
        const __half2* h = (const __half2*)&v;
        #pragma unroll
        for (int j = 0; j < 4; j++) {
            float2 p = __half22float2(h[j]);
            ss += p.x*p.x + p.y*p.y;
        }
    }
    #pragma unroll
    for (int o = 16; o > 0; o >>= 1) ss += __shfl_xor_sync(~0u, ss, o);
    if (lane == 0) rinv[tok] = rsqrtf(ss * (1.0f / DD) + EPSR);
}

// ---------------- fused SSM scan: decoupled lookback; fp16 x_ssm output only ----------------
__global__ __launch_bounds__(128) void scan_fused(
    const float* __restrict__ x, const float* __restrict__ rinv,
    const float* __restrict__ n1w, const float* __restrict__ b_w,
    const float* __restrict__ a_raw, const float* __restrict__ c_w,
    float* __restrict__ agg, float* __restrict__ incl, int* __restrict__ flags,
    __half* __restrict__ xh)
{
    int blk = blockIdx.x;            // b*NCHUNK + c
    int half = blockIdx.y;
    int c = blk & (NCHUNK - 1);
    int t = threadIdx.x;
    int d4 = half * 128 + t;
    int fidx = blk * 2 + half;
    int tok0 = blk * CHUNK;

    float4 w1 = ((const float4*)n1w)[d4];
    float4 w2 = ((const float4*)b_w)[d4];
    float4 wc = { w1.x*w2.x, w1.y*w2.y, w1.z*w2.z, w1.w*w2.w };
    float4 cw = ((const float4*)c_w)[d4];
    float4 ar = ((const float4*)a_raw)[d4];
    float a0 = sigmoidf_(ar.x), a1 = sigmoidf_(ar.y), a2 = sigmoidf_(ar.z), a3 = sigmoidf_(ar.w);
    float aC0 = a0, aC1 = a1, aC2 = a2, aC3 = a3;
    #pragma unroll
    for (int i = 0; i < 6; i++) { aC0 *= aC0; aC1 *= aC1; aC2 *= aC2; aC3 *= aC3; }

    const float4* xp = (const float4*)(x + (size_t)tok0 * DD) + d4;
    const float* rp = rinv + tok0;

    float h0 = 0.f, h1 = 0.f, h2 = 0.f, h3 = 0.f;
    #pragma unroll 4
    for (int i = 0; i < CHUNK; i++) {
        float r = rp[i];
        float4 xv = xp[(size_t)i * 256];
        h0 = fmaf(a0, h0, xv.x * r * wc.x);
        h1 = fmaf(a1, h1, xv.y * r * wc.y);
        h2 = fmaf(a2, h2, xv.z * r * wc.z);
        h3 = fmaf(a3, h3, xv.w * r * wc.w);
    }

    float e0 = 0.f, e1 = 0.f, e2 = 0.f, e3 = 0.f;
    __shared__ int sflag;
    if (c == 0) {
        float4 iv = { h0, h1, h2, h3 };
        ((float4*)(incl + (size_t)blk * DD))[d4] = iv;
        __threadfence();
        __syncthreads();
        if (t == 0) atomicExch(&flags[fidx], 2);
    } else {
        float4 av = { h0, h1, h2, h3 };
        ((float4*)(agg + (size_t)blk * DD))[d4] = av;
        __threadfence();
        __syncthreads();
        if (t == 0) atomicExch(&flags[fidx], 1);
        float f0 = 1.f, f1 = 1.f, f2 = 1.f, f3 = 1.f;
        int j = blk - 1;
        while (true) {
            if (t == 0) {
                int fl;
                do { fl = atomicOr(&flags[j * 2 + half], 0); } while (fl == 0);
                sflag = fl;
            }
            __syncthreads();
            int fl = sflag;
            __threadfence();
            if (fl == 2) {
                float4 pv = ((const float4*)(incl + (size_t)j * DD))[d4];
                e0 = fmaf(f0, pv.x, e0); e1 = fmaf(f1, pv.y, e1);
                e2 = fmaf(f2, pv.z, e2); e3 = fmaf(f3, pv.w, e3);
                break;
            } else {
                float4 pv = ((const float4*)(agg + (size_t)j * DD))[d4];
                e0 = fmaf(f0, pv.x, e0); e1 = fmaf(f1, pv.y, e1);
                e2 = fmaf(f2, pv.z, e2); e3 = fmaf(f3, pv.w, e3);
                f0 *= aC0; f1 *= aC1; f2 *= aC2; f3 *= aC3;
                j--;
            }
            __syncthreads();
        }
        float4 iv = { fmaf(aC0, e0, h0), fmaf(aC1, e1, h1),
                      fmaf(aC2, e2, h2), fmaf(aC3, e3, h3) };
        ((float4*)(incl + (size_t)blk * DD))[d4] = iv;
        __threadfence();
        __syncthreads();
        if (t == 0) atomicExch(&flags[fidx], 2);
    }

    h0 = e0; h1 = e1; h2 = e2; h3 = e3;
    #pragma unroll 4
    for (int i = 0; i < CHUNK; i++) {
        float r = rp[i];
        float4 xv = xp[(size_t)i * 256];
        h0 = fmaf(a0, h0, xv.x * r * wc.x);
        h1 = fmaf(a1, h1, xv.y * r * wc.y);
        h2 = fmaf(a2, h2, xv.z * r * wc.z);
        h3 = fmaf(a3, h3, xv.w * r * wc.w);
        size_t ho = ((size_t)tok0 + i) * DD + (size_t)d4 * 4;
        *(__half2*)(xh + ho)     = __floats2half2_rn(xv.x + h0 * cw.x, xv.y + h1 * cw.y);
        *(__half2*)(xh + ho + 2) = __floats2half2_rn(xv.z + h2 * cw.z, xv.w + h3 * cw.w);
    }
}

// ---------------- warp-per-token sliding-window attention: 64 tokens/block ----------------
#define KV_STRIDE 66
#define ATTN_KS   0
#define ATTN_VS   16768
#define ATTN_QS   33536
#define ATTN_PS   35584
#define ATTN_SMEM 37632

__global__ __launch_bounds__(256) void attn_kernel(const __half* __restrict__ QKV,
                                                   const float* __restrict__ bias,
                                                   __half* __restrict__ ga) {
    extern __shared__ __align__(16) char smem[];
    __half* Ks = (__half*)(smem + ATTN_KS);
    __half* Vs = (__half*)(smem + ATTN_VS);
    float*  qs = (float*)(smem + ATTN_QS);
    float*  ps = (float*)(smem + ATTN_PS);

    int tok0 = blockIdx.x * 64;
    int b = tok0 / LL, l0 = tok0 % LL;
    int tid = threadIdx.x, lane = tid & 31, warp = tid >> 5;
    float gb = bias[0];

    for (int idx = tid; idx < 127 * 32; idx += 256) {
        int s = idx >> 5, dp = idx & 31;
        int r = l0 - 63 + s;
        __half2 kk = __floats2half2_rn(0.f, 0.f), vv = kk;
        if (r >= 0) {
            const __half* row = QKV + ((size_t)b * LL + r) * QKVN;
            kk = *(const __half2*)(row + 64 + dp * 2);
            vv = *(const __half2*)(row + 128 + dp * 2);
        }
        *(__half2*)(Ks + s * KV_STRIDE + dp * 2) = kk;
        *(__half2*)(Vs + s * KV_STRIDE + dp * 2) = vv;
    }
    __syncthreads();

    float* qw = qs + warp * 64;
    float* pw = ps + warp * 64;

    for (int it = 0; it < 8; it++) {
        int i = it * 8 + warp;
        int tkn = tok0 + i;
        const __half* qrow = QKV + (size_t)tkn * QKVN;
        qw[lane] = __half2float(qrow[lane]);
        qw[lane + 32] = __half2float(qrow[lane + 32]);
        float sg = 0.f;
        if (lane == 0) sg = sigmoidf_(__half2float(qrow[192]) + gb);
        sg = __shfl_sync(~0u, sg, 0);
        __syncwarp();

        int w0 = lane * 2;
        float s0 = 0.f, s1 = 0.f;
        const __half* k0 = Ks + (i + w0) * KV_STRIDE;
        const __half* k1 = k0 + KV_STRIDE;
        #pragma unroll 8
        for (int d = 0; d < AD; d += 2) {
            float q0 = qw[d], q1 = qw[d + 1];
            float2 ka = __half22float2(*(const __half2*)(k0 + d));
            float2 kb = __half22float2(*(const __half2*)(k1 + d));
            s0 = fmaf(q0, ka.x, fmaf(q1, ka.y, s0));
            s1 = fmaf(q0, kb.x, fmaf(q1, kb.y, s1));
        }
        bool v0 = (l0 + i - 63 + w0) >= 0;
        bool v1 = (l0 + i - 62 + w0) >= 0;
        s0 = v0 ? s0 * 0.125f : -INFINITY;
        s1 = v1 ? s1 * 0.125f : -INFINITY;
        float m = fmaxf(s0, s1);
        #pragma unroll
        for (int o = 16; o > 0; o >>= 1) m = fmaxf(m, __shfl_xor_sync(~0u, m, o));
        float e0 = v0 ? expf(s0 - m) : 0.f;
        float e1 = v1 ? expf(s1 - m) : 0.f;
        float sum = e0 + e1;
        #pragma unroll
        for (int o = 16; o > 0; o >>= 1) sum += __shfl_xor_sync(~0u, sum, o);
        float inv = sg / sum;
        *(float2*)(pw + w0) = make_float2(e0, e1);
        __syncwarp();

        float a0 = 0.f, a1 = 0.f;
        #pragma unroll 8
        for (int w = 0; w < WW; w++) {
            float p = pw[w];
            float2 vv = __half22float2(*(const __half2*)(Vs + (i + w) * KV_STRIDE + w0));
            a0 = fmaf(p, vv.x, a0);
            a1 = fmaf(p, vv.y, a1);
        }
        *(__half2*)(ga + (size_t)tkn * AD + w0) = __floats2half2_rn(a0 * inv, a1 * inv);
        __syncwarp();
    }
}

// ---------------- launcher ----------------
extern "C" void kernel_launch(void* const* d_in, const int* in_sizes, int n_in,
                              void* d_out, int out_size) {
    (void)in_sizes; (void)n_in; (void)out_size;
    const float* x     = (const float*)d_in[0];
    const float* n1w   = (const float*)d_in[1];
    const float* n2w   = (const float*)d_in[2];
    const float* a_raw = (const float*)d_in[3];
    const float* b_w   = (const float*)d_in[4];
    const float* c_w   = (const float*)d_in[5];
    const float* Wq    = (const float*)d_in[6];
    const float* Wk    = (const float*)d_in[7];
    const float* Wv    = (const float*)d_in[8];
    const float* Wo    = (const float*)d_in[9];
    const float* Wg    = (const float*)d_in[10];
    const float* gbias = (const float*)d_in[11];
    const float* ff1   = (const float*)d_in[12];
    const float* ff2   = (const float*)d_in[13];
    float* out = (float*)d_out;

    float *p_rinv, *p_agg, *p_incl;
    int *p_flags;
    __half *p_xh, *p_tmp, *p_ga, *p_qkvh, *p_wqkv, *p_woT, *p_f1T, *p_f2T;
    cudaGetSymbolAddress((void**)&p_rinv, g_rinv);
    cudaGetSymbolAddress((void**)&p_agg, g_agg);
    cudaGetSymbolAddress((void**)&p_incl, g_incl);
    cudaGetSymbolAddress((void**)&p_flags, g_flags);
    cudaGetSymbolAddress((void**)&p_xh, g_xh);
    cudaGetSymbolAddress((void**)&p_tmp, g_tmp);
    cudaGetSymbolAddress((void**)&p_ga, g_ga);
    cudaGetSymbolAddress((void**)&p_qkvh, g_qkvh);
    cudaGetSymbolAddress((void**)&p_wqkv, g_wqkvT);
    cudaGetSymbolAddress((void**)&p_woT, g_woT);
    cudaGetSymbolAddress((void**)&p_f1T, g_f1T);
    cudaGetSymbolAddress((void**)&p_f2T, g_f2T);

    const int SMEM_8 = 3 * (16384 + 16384);  // 98304
    const int SMEM_4 = 3 * (16384 + 16384);  // 98304
    cudaFuncSetAttribute(mma_gemm8<1>, cudaFuncAttributeMaxDynamicSharedMemorySize, SMEM_8);
    cudaFuncSetAttribute(mma_gemm8<2>, cudaFuncAttributeMaxDynamicSharedMemorySize, SMEM_8);
    cudaFuncSetAttribute(mma_gemm8<3>, cudaFuncAttributeMaxDynamicSharedMemorySize, SMEM_8);
    cudaFuncSetAttribute(mma_gemm4, cudaFuncAttributeMaxDynamicSharedMemorySize, SMEM_4);
    cudaFuncSetAttribute(attn_kernel, cudaFuncAttributeMaxDynamicSharedMemorySize, ATTN_SMEM);

    // 0) weight prep (f1T folds n2w) + rms of x + flags reset (single launch)
    prep_kernel<<<4416 + 2048, dim3(32, 8)>>>(Wq, Wk, Wv, Wg, Wo, ff1, ff2, n2w, x,
                                              p_wqkv, p_woT, p_f1T, p_f2T, p_rinv, p_flags);
    // 1) fused decoupled-lookback SSM scan -> fp16 x_ssm
    scan_fused<<<dim3(BB * NCHUNK, 2), 128>>>(x, p_rinv, n1w, b_w, a_raw, c_w,
                                              p_agg, p_incl, p_flags, p_xh);
    // 2) fused QKV+gate projection -> fp16 (4-warp crossbar-optimal)
    {
        dim3 grid(QKVN / 128, MROWS / 128);
        mma_gemm4<<<grid, 128, SMEM_4>>>(QKVN, DD, p_xh, p_wqkv, p_qkvh);
    }
    // 3) attention + gate -> ga fp16 (64 tokens/block)
    attn_kernel<<<MROWS / 64, 256, ATTN_SMEM>>>(p_qkvh, gbias, p_ga);
    // 4) xh += ga @ WoT (fp16 residual, in-place)
    {
        dim3 grid(DD / 128, MROWS / 128);
        mma_gemm8<3><<<grid, 256, SMEM_8>>>(DD, AD, p_ga, p_woT, nullptr, p_xh, p_xh, nullptr);
    }
    // 5) rinv2 over xh (reuses g_rinv)
    rms2h_kernel<<<MROWS / 8, 256>>>(p_xh, p_rinv);
    // 6) tmp = silu(rinv2(row) * (xh @ f1T)) -> fp16   (n2w folded into f1T)
    {
        dim3 grid(FFD / 128, MROWS / 128);
        mma_gemm8<1><<<grid, 256, SMEM_8>>>(FFD, DD, p_xh, p_f1T, nullptr, p_tmp, nullptr, p_rinv);
    }
    // 7) out = xh + tmp @ ff_w2 (fp32 output)
    {
        dim3 grid(DD / 128, MROWS / 128);
        mma_gemm8<2><<<grid, 256, SMEM_8>>>(DD, FFD, p_tmp, p_f2T, out, nullptr, p_xh, nullptr);
    }
}